// round 1
// baseline (speedup 1.0000x reference)
#include <cuda_runtime.h>

#define NMAX 500000
#define GMAX 5000
#define HID 64
#define H1  128

// Scratch (static __device__ per allocation rules)
__device__ float4 d_agg[NMAX];           // (1+eps)*x + sum_{j->i} x_j
__device__ float  d_sums[GMAX * HID];    // per-graph h2 sums
__device__ float  d_W1[H1 * 4];          // folded W1, column-major [j][k]
__device__ float  d_C1[H1];              // folded bias1 (BN folded)
__device__ float  d_W2t[H1 * HID];       // folded W2, tf32-rounded, [j][o]
__device__ float  d_C2[HID];             // folded bias2

__device__ __forceinline__ unsigned f2tf(float f) {
    unsigned r;
    asm("cvt.rna.tf32.f32 %0, %1;" : "=r"(r) : "f"(f));
    return r;
}

__device__ __forceinline__ void red4(float4* p, float4 v) {
    asm volatile("red.global.add.v4.f32 [%0], {%1, %2, %3, %4};"
                 :: "l"(p), "f"(v.x), "f"(v.y), "f"(v.z), "f"(v.w)
                 : "memory");
}

// ---------------------------------------------------------------------------
// Prep: fold BN into weights, zero pooling accumulators.
// ---------------------------------------------------------------------------
__global__ void prep_kernel(const float* __restrict__ w1, const float* __restrict__ b1,
                            const float* __restrict__ g1, const float* __restrict__ be1,
                            const float* __restrict__ m1, const float* __restrict__ v1,
                            const float* __restrict__ w2, const float* __restrict__ b2,
                            const float* __restrict__ g2, const float* __restrict__ be2,
                            const float* __restrict__ m2, const float* __restrict__ v2,
                            int G) {
    int idx = blockIdx.x * blockDim.x + threadIdx.x;
    if (idx < G * HID) d_sums[idx] = 0.f;
    if (idx < H1 * HID) {
        int o = idx & 63;
        float s2 = g2[o] * rsqrtf(v2[o] + 1e-5f);
        d_W2t[idx] = __uint_as_float(f2tf(w2[idx] * s2));
    }
    if (idx < H1) {
        float s1 = g1[idx] * rsqrtf(v1[idx] + 1e-5f);
        #pragma unroll
        for (int k = 0; k < 4; k++) d_W1[idx * 4 + k] = w1[k * H1 + idx] * s1;
        d_C1[idx] = (b1[idx] - m1[idx]) * s1 + be1[idx];
    }
    if (idx < HID) {
        float s2 = g2[idx] * rsqrtf(v2[idx] + 1e-5f);
        d_C2[idx] = (b2[idx] - m2[idx]) * s2 + be2[idx];
    }
}

// ---------------------------------------------------------------------------
// Init: agg[i] = (1+eps) * x[i]
// ---------------------------------------------------------------------------
__global__ void init_kernel(const float4* __restrict__ x, const float* __restrict__ epsp, int n) {
    int i = blockIdx.x * blockDim.x + threadIdx.x;
    if (i < n) {
        float c = 1.f + *epsp;
        float4 v = x[i];
        v.x *= c; v.y *= c; v.z *= c; v.w *= c;
        d_agg[i] = v;
    }
}

// ---------------------------------------------------------------------------
// Edge scatter: agg[dst] += x[src], one vectorized RED per edge, 4 edges/thread
// ---------------------------------------------------------------------------
__global__ void edge_kernel(const int* __restrict__ ei, const float4* __restrict__ x, int E) {
    int t = blockIdx.x * blockDim.x + threadIdx.x;
    int e = t * 4;
    if (e + 3 < E) {
        int4 s = *reinterpret_cast<const int4*>(ei + e);
        int4 d = *reinterpret_cast<const int4*>(ei + E + e);
        float4 v0 = __ldg(x + s.x);
        float4 v1 = __ldg(x + s.y);
        float4 v2 = __ldg(x + s.z);
        float4 v3 = __ldg(x + s.w);
        red4(&d_agg[d.x], v0);
        red4(&d_agg[d.y], v1);
        red4(&d_agg[d.z], v2);
        red4(&d_agg[d.w], v3);
    } else if (e < E) {
        for (int q = e; q < E; q++) {
            int s = ei[q], d = ei[E + q];
            red4(&d_agg[d], __ldg(x + s));
        }
    }
}

// ---------------------------------------------------------------------------
// Fused MLP + pool. 128 nodes per block, 256 threads (8 warps).
// Layer1 (K=4) scalar -> A fragments generated directly in mma register
// layout. Layer2 via tf32 mma.sync m16n8k8 (M=16 rows/warp, N=64, K=128).
// Pool via shared segmented scan (batch is sorted) + few global atomics.
// ---------------------------------------------------------------------------
__global__ void __launch_bounds__(256, 2)
mlp_kernel(const int* __restrict__ batch, int n) {
    __shared__ float  W2s[H1 * 72];   // padded stride 72 -> conflict-free B loads
    __shared__ float4 W1s[H1];
    __shared__ float  C1s[H1];
    __shared__ float  C2s[HID];
    __shared__ int    batchs[128];

    int tid = threadIdx.x;
    int blockStart = blockIdx.x * 128;

    for (int i = tid; i < H1 * HID; i += 256) {
        int j = i >> 6, o = i & 63;
        W2s[j * 72 + o] = d_W2t[i];
    }
    if (tid < H1) {
        W1s[tid] = *reinterpret_cast<const float4*>(&d_W1[tid * 4]);
        C1s[tid] = d_C1[tid];
    }
    if (tid < HID) C2s[tid] = d_C2[tid];
    if (tid < 128) {
        int nd = blockStart + tid;
        batchs[tid] = (nd < n) ? batch[nd] : -1;
    }
    __syncthreads();

    int lane = tid & 31, warp = tid >> 5;
    int grp = lane >> 2;      // threadID / 4
    int kc  = lane & 3;       // threadID % 4
    int r0l = warp * 16 + grp;
    int r1l = r0l + 8;
    int n0 = blockStart + r0l;
    int n1 = blockStart + r1l;
    float4 h0a = d_agg[min(n0, n - 1)];
    float4 h0b = d_agg[min(n1, n - 1)];

    float acc[8][4];
    #pragma unroll
    for (int i = 0; i < 8; i++) { acc[i][0] = acc[i][1] = acc[i][2] = acc[i][3] = 0.f; }

    #pragma unroll
    for (int p = 0; p < 2; p++) {
        // layer1: compute the 32 h1 values this thread needs for A fragments
        unsigned A0[16], A1[16];
        #pragma unroll
        for (int t = 0; t < 16; t++) {
            int col = p * 64 + t * 4 + kc;
            float4 w = W1s[col];
            float c = C1s[col];
            float u0 = fmaf(h0a.w, w.w, fmaf(h0a.z, w.z, fmaf(h0a.y, w.y, fmaf(h0a.x, w.x, c))));
            float u1 = fmaf(h0b.w, w.w, fmaf(h0b.z, w.z, fmaf(h0b.y, w.y, fmaf(h0b.x, w.x, c))));
            A0[t] = f2tf(fmaxf(u0, 0.f));
            A1[t] = f2tf(fmaxf(u1, 0.f));
        }
        // layer2: 8 K-steps of m16n8k8 over N=64 (8 n-tiles)
        #pragma unroll
        for (int s = 0; s < 8; s++) {
            unsigned a0 = A0[2 * s], a1 = A1[2 * s], a2 = A0[2 * s + 1], a3 = A1[2 * s + 1];
            int kk = p * 64 + 8 * s;
            const float* bp = &W2s[(kk + kc) * 72 + grp];
            #pragma unroll
            for (int nt = 0; nt < 8; nt++) {
                unsigned b0 = __float_as_uint(bp[nt * 8]);
                unsigned b1 = __float_as_uint(bp[nt * 8 + 4 * 72]);
                asm volatile(
                    "mma.sync.aligned.m16n8k8.row.col.f32.tf32.tf32.f32 "
                    "{%0,%1,%2,%3},{%4,%5,%6,%7},{%8,%9},{%0,%1,%2,%3};"
                    : "+f"(acc[nt][0]), "+f"(acc[nt][1]), "+f"(acc[nt][2]), "+f"(acc[nt][3])
                    : "r"(a0), "r"(a1), "r"(a2), "r"(a3), "r"(b0), "r"(b1));
            }
        }
    }

    __syncthreads();                 // everyone done reading W2s
    float* h2s = W2s;                // reuse as h2 [128][65]
    #pragma unroll
    for (int nt = 0; nt < 8; nt++) {
        int c = nt * 8 + 2 * kc;
        h2s[r0l * 65 + c]     = fmaxf(acc[nt][0] + C2s[c],     0.f);
        h2s[r0l * 65 + c + 1] = fmaxf(acc[nt][1] + C2s[c + 1], 0.f);
        h2s[r1l * 65 + c]     = fmaxf(acc[nt][2] + C2s[c],     0.f);
        h2s[r1l * 65 + c + 1] = fmaxf(acc[nt][3] + C2s[c + 1], 0.f);
    }
    __syncthreads();

    // segmented pooling scan: thread = (column, node-quarter)
    int col = tid & 63, part = tid >> 6;
    float run = 0.f;
    int curg = -1;
    #pragma unroll 1
    for (int ln = part * 32; ln < part * 32 + 32; ln++) {
        if (blockStart + ln >= n) break;
        int g = batchs[ln];
        if (g != curg) {
            if (curg >= 0) atomicAdd(&d_sums[curg * HID + col], run);
            run = 0.f;
            curg = g;
        }
        run += h2s[ln * 65 + col];
    }
    if (curg >= 0) atomicAdd(&d_sums[curg * HID + col], run);
}

// ---------------------------------------------------------------------------
// Final: per-graph mean, 64->2 head, stable log_softmax. Counts via binary
// search on the sorted batch array.
// ---------------------------------------------------------------------------
__global__ void final_kernel(const float* __restrict__ w3, const float* __restrict__ b3,
                             const int* __restrict__ batch, float* __restrict__ out,
                             int n, int G) {
    int g = blockIdx.x * blockDim.x + threadIdx.x;
    if (g >= G) return;
    int lo = 0, hi = n;
    while (lo < hi) { int mid = (lo + hi) >> 1; if (batch[mid] < g) lo = mid + 1; else hi = mid; }
    int a = lo;
    hi = n;
    while (lo < hi) { int mid = (lo + hi) >> 1; if (batch[mid] < g + 1) lo = mid + 1; else hi = mid; }
    int cnt = lo - a;
    float inv = 1.f / fmaxf((float)cnt, 1.f);

    float l0 = b3[0], l1 = b3[1];
    const float* sp = &d_sums[g * HID];
    #pragma unroll
    for (int o = 0; o < HID; o++) {
        float pv = sp[o] * inv;
        l0 = fmaf(pv, w3[2 * o],     l0);
        l1 = fmaf(pv, w3[2 * o + 1], l1);
    }
    float m = fmaxf(l0, l1);
    float lse = m + logf(expf(l0 - m) + expf(l1 - m));
    out[2 * g]     = l0 - lse;
    out[2 * g + 1] = l1 - lse;
}

// ---------------------------------------------------------------------------
extern "C" void kernel_launch(void* const* d_in, const int* in_sizes, int n_in,
                              void* d_out, int out_size) {
    const float* x   = (const float*)d_in[0];
    const float* eps = (const float*)d_in[1];
    const float* w1  = (const float*)d_in[2];
    const float* b1  = (const float*)d_in[3];
    const float* g1  = (const float*)d_in[4];
    const float* be1 = (const float*)d_in[5];
    const float* m1  = (const float*)d_in[6];
    const float* v1  = (const float*)d_in[7];
    const float* w2  = (const float*)d_in[8];
    const float* b2  = (const float*)d_in[9];
    const float* g2  = (const float*)d_in[10];
    const float* be2 = (const float*)d_in[11];
    const float* m2  = (const float*)d_in[12];
    const float* v2  = (const float*)d_in[13];
    const float* w3  = (const float*)d_in[14];
    const float* b3  = (const float*)d_in[15];
    const int*   ei  = (const int*)d_in[16];
    const int*   batch = (const int*)d_in[17];

    int n = in_sizes[0] / 4;
    int E = in_sizes[16] / 2;
    int G = out_size / 2;

    prep_kernel<<<(G * HID + 255) / 256, 256>>>(w1, b1, g1, be1, m1, v1,
                                                w2, b2, g2, be2, m2, v2, G);
    init_kernel<<<(n + 255) / 256, 256>>>((const float4*)x, eps, n);
    int et = (E + 3) / 4;
    edge_kernel<<<(et + 255) / 256, 256>>>(ei, (const float4*)x, E);
    mlp_kernel<<<(n + 127) / 128, 256>>>(batch, n);
    final_kernel<<<(G + 255) / 256, 256>>>(w3, b3, batch, (float*)d_out, n, G);
}

// round 2
// speedup vs baseline: 1.0316x; 1.0316x over previous
#include <cuda_runtime.h>

#define NMAX 500000
#define GMAX 5000
#define HID 64
#define H1  128

// Scratch (static __device__ per allocation rules)
__device__ float4 d_agg[NMAX];           // (1+eps)*x + sum_{j->i} x_j
__device__ float  d_sums[GMAX * HID];    // per-graph h2 sums
__device__ float  d_W1[H1 * 4];          // folded W1, column-major [j][k]
__device__ float  d_C1[H1];              // folded bias1 (BN folded)
__device__ float  d_Bfrag[32 * 256];     // W2 in per-lane mma fragment order
__device__ float  d_C2[HID];             // folded bias2

__device__ __forceinline__ unsigned f2tf(float f) {
    unsigned r;
    asm("cvt.rna.tf32.f32 %0, %1;" : "=r"(r) : "f"(f));
    return r;
}

__device__ __forceinline__ void red4(float4* p, float4 v) {
    asm volatile("red.global.add.v4.f32 [%0], {%1, %2, %3, %4};"
                 :: "l"(p), "f"(v.x), "f"(v.y), "f"(v.z), "f"(v.w)
                 : "memory");
}

__device__ __forceinline__ void mma_tf32(float* c, unsigned a0, unsigned a1,
                                         unsigned a2, unsigned a3,
                                         unsigned b0, unsigned b1) {
    asm volatile(
        "mma.sync.aligned.m16n8k8.row.col.f32.tf32.tf32.f32 "
        "{%0,%1,%2,%3},{%4,%5,%6,%7},{%8,%9},{%0,%1,%2,%3};"
        : "+f"(c[0]), "+f"(c[1]), "+f"(c[2]), "+f"(c[3])
        : "r"(a0), "r"(a1), "r"(a2), "r"(a3), "r"(b0), "r"(b1));
}

// ---------------------------------------------------------------------------
// Prep: fold BN into weights, pre-swizzle W2 into mma B-fragment order,
// zero pooling accumulators.
// Fragment order per lane l (kc=l&3, grp=l>>2): seq q = s*16 + nt*2 + j
//   value = W2fold[k = 8s + kc + 4j][o = 8nt + grp]
// ---------------------------------------------------------------------------
__global__ void prep_kernel(const float* __restrict__ w1, const float* __restrict__ b1,
                            const float* __restrict__ g1, const float* __restrict__ be1,
                            const float* __restrict__ m1, const float* __restrict__ v1,
                            const float* __restrict__ w2, const float* __restrict__ b2,
                            const float* __restrict__ g2, const float* __restrict__ be2,
                            const float* __restrict__ m2, const float* __restrict__ v2,
                            int G) {
    int idx = blockIdx.x * blockDim.x + threadIdx.x;
    if (idx < G * HID) d_sums[idx] = 0.f;
    if (idx < 32 * 256) {
        int l = idx >> 8, q = idx & 255;
        int kc = l & 3, grp = l >> 2;
        int s = q >> 4, r = q & 15, nt = r >> 1, j = r & 1;
        int k = 8 * s + kc + 4 * j;
        int o = 8 * nt + grp;
        float s2 = g2[o] * rsqrtf(v2[o] + 1e-5f);
        d_Bfrag[idx] = __uint_as_float(f2tf(w2[k * HID + o] * s2));
    }
    if (idx < H1) {
        float s1 = g1[idx] * rsqrtf(v1[idx] + 1e-5f);
        #pragma unroll
        for (int k = 0; k < 4; k++) d_W1[idx * 4 + k] = w1[k * H1 + idx] * s1;
        d_C1[idx] = (b1[idx] - m1[idx]) * s1 + be1[idx];
    }
    if (idx < HID) {
        float s2 = g2[idx] * rsqrtf(v2[idx] + 1e-5f);
        d_C2[idx] = (b2[idx] - m2[idx]) * s2 + be2[idx];
    }
}

// ---------------------------------------------------------------------------
// Init: agg[i] = (1+eps) * x[i]
// ---------------------------------------------------------------------------
__global__ void init_kernel(const float4* __restrict__ x, const float* __restrict__ epsp, int n) {
    int i = blockIdx.x * blockDim.x + threadIdx.x;
    if (i < n) {
        float c = 1.f + *epsp;
        float4 v = x[i];
        v.x *= c; v.y *= c; v.z *= c; v.w *= c;
        d_agg[i] = v;
    }
}

// ---------------------------------------------------------------------------
// Edge scatter: agg[dst] += x[src], one vectorized RED per edge, 8 edges/thread
// ---------------------------------------------------------------------------
__global__ void edge_kernel(const int* __restrict__ ei, const float4* __restrict__ x, int E) {
    int t = blockIdx.x * blockDim.x + threadIdx.x;
    int e = t * 8;
    if (e + 7 < E) {
        int4 s0 = *reinterpret_cast<const int4*>(ei + e);
        int4 s1 = *reinterpret_cast<const int4*>(ei + e + 4);
        int4 d0 = *reinterpret_cast<const int4*>(ei + E + e);
        int4 d1 = *reinterpret_cast<const int4*>(ei + E + e + 4);
        float4 v0 = __ldg(x + s0.x);
        float4 v1 = __ldg(x + s0.y);
        float4 v2 = __ldg(x + s0.z);
        float4 v3 = __ldg(x + s0.w);
        float4 v4 = __ldg(x + s1.x);
        float4 v5 = __ldg(x + s1.y);
        float4 v6 = __ldg(x + s1.z);
        float4 v7 = __ldg(x + s1.w);
        red4(&d_agg[d0.x], v0);
        red4(&d_agg[d0.y], v1);
        red4(&d_agg[d0.z], v2);
        red4(&d_agg[d0.w], v3);
        red4(&d_agg[d1.x], v4);
        red4(&d_agg[d1.y], v5);
        red4(&d_agg[d1.z], v6);
        red4(&d_agg[d1.w], v7);
    } else if (e < E) {
        for (int q = e; q < E; q++) {
            int s = ei[q], d = ei[E + q];
            red4(&d_agg[d], __ldg(x + s));
        }
    }
}

// ---------------------------------------------------------------------------
// Fused MLP + pool. 256 nodes per block, 256 threads (8 warps).
// Warp w owns rows [32w, 32w+32): two m16 tiles sharing every B fragment.
// B pre-swizzled in fragment order -> 64 conflict-free LDS.128 per thread.
// Layer1 (K=4) scalar, A fragments generated directly in registers.
// Dynamic smem: B stage (reused as h2 staging) + W1/C1/C2/batch.
// ---------------------------------------------------------------------------
#define SM_H2F (256 * 65)     // floats for h2 staging (union with B stage)
#define MLP_SMEM ((SM_H2F + 512 + 128 + 64 + 256) * 4)

__global__ void __launch_bounds__(256, 2)
mlp_kernel(const int* __restrict__ batch, int n) {
    extern __shared__ float sm[];
    float*  Bf   = sm;                                  // [32][260] padded
    float4* W1s  = (float4*)(sm + SM_H2F);              // 128 float4
    float*  C1s  = sm + SM_H2F + 512;
    float*  C2s  = C1s + 128;
    int*    batchs = (int*)(C2s + 64);

    int tid = threadIdx.x;
    int blockStart = blockIdx.x * 256;

    for (int i = tid; i < 32 * 256; i += 256) {
        int l = i >> 8, q = i & 255;
        Bf[l * 260 + q] = d_Bfrag[i];
    }
    if (tid < H1) {
        W1s[tid] = *reinterpret_cast<const float4*>(&d_W1[tid * 4]);
        C1s[tid] = d_C1[tid];
    }
    if (tid < HID) C2s[tid] = d_C2[tid];
    {
        int nd = blockStart + tid;
        batchs[tid] = (nd < n) ? batch[nd] : -1;
    }
    __syncthreads();

    int lane = tid & 31, warp = tid >> 5;
    int grp = lane >> 2;      // lane / 4
    int kc  = lane & 3;       // lane % 4
    int rbase = blockStart + warp * 32 + grp;

    float4 h0[4];
    #pragma unroll
    for (int t = 0; t < 4; t++) h0[t] = d_agg[min(rbase + t * 8, n - 1)];

    float acc[2][8][4];
    #pragma unroll
    for (int t = 0; t < 2; t++)
        #pragma unroll
        for (int nt = 0; nt < 8; nt++)
            #pragma unroll
            for (int i = 0; i < 4; i++) acc[t][nt][i] = 0.f;

    const float4* bptr = (const float4*)(Bf + lane * 260);

    #pragma unroll
    for (int s = 0; s < 16; s++) {
        int c0 = 8 * s + kc, c1 = c0 + 4;
        float4 wA = W1s[c0]; float cA = C1s[c0];
        float4 wB = W1s[c1]; float cB = C1s[c1];
        unsigned a0[2], a1[2], a2[2], a3[2];
        #pragma unroll
        for (int t = 0; t < 2; t++) {
            float4 hl = h0[2 * t];
            float4 hh = h0[2 * t + 1];
            float uA0 = fmaf(hl.w, wA.w, fmaf(hl.z, wA.z, fmaf(hl.y, wA.y, fmaf(hl.x, wA.x, cA))));
            float uA1 = fmaf(hh.w, wA.w, fmaf(hh.z, wA.z, fmaf(hh.y, wA.y, fmaf(hh.x, wA.x, cA))));
            float uB0 = fmaf(hl.w, wB.w, fmaf(hl.z, wB.z, fmaf(hl.y, wB.y, fmaf(hl.x, wB.x, cB))));
            float uB1 = fmaf(hh.w, wB.w, fmaf(hh.z, wB.z, fmaf(hh.y, wB.y, fmaf(hh.x, wB.x, cB))));
            a0[t] = f2tf(fmaxf(uA0, 0.f));
            a1[t] = f2tf(fmaxf(uA1, 0.f));
            a2[t] = f2tf(fmaxf(uB0, 0.f));
            a3[t] = f2tf(fmaxf(uB1, 0.f));
        }
        #pragma unroll
        for (int np = 0; np < 4; np++) {
            float4 bv = bptr[s * 4 + np];
            unsigned bx = __float_as_uint(bv.x), by = __float_as_uint(bv.y);
            unsigned bz = __float_as_uint(bv.z), bw = __float_as_uint(bv.w);
            #pragma unroll
            for (int t = 0; t < 2; t++) {
                mma_tf32(acc[t][2 * np],     a0[t], a1[t], a2[t], a3[t], bx, by);
                mma_tf32(acc[t][2 * np + 1], a0[t], a1[t], a2[t], a3[t], bz, bw);
            }
        }
    }

    __syncthreads();                 // all B reads complete; reuse as h2 staging
    float* h2s = sm;                 // [256][65]
    int r0l = warp * 32 + grp;
    #pragma unroll
    for (int t = 0; t < 2; t++) {
        int rl = r0l + 16 * t;
        #pragma unroll
        for (int nt = 0; nt < 8; nt++) {
            int c = nt * 8 + 2 * kc;
            h2s[rl * 65 + c]           = fmaxf(acc[t][nt][0] + C2s[c],     0.f);
            h2s[rl * 65 + c + 1]       = fmaxf(acc[t][nt][1] + C2s[c + 1], 0.f);
            h2s[(rl + 8) * 65 + c]     = fmaxf(acc[t][nt][2] + C2s[c],     0.f);
            h2s[(rl + 8) * 65 + c + 1] = fmaxf(acc[t][nt][3] + C2s[c + 1], 0.f);
        }
    }
    __syncthreads();

    // segmented pooling scan: thread = (column, node-quarter of 64 rows)
    int col = tid & 63, part = tid >> 6;
    float run = 0.f;
    int curg = -1;
    #pragma unroll 1
    for (int ln = part * 64; ln < part * 64 + 64; ln++) {
        if (blockStart + ln >= n) break;
        int g = batchs[ln];
        if (g != curg) {
            if (curg >= 0) atomicAdd(&d_sums[curg * HID + col], run);
            run = 0.f;
            curg = g;
        }
        run += h2s[ln * 65 + col];
    }
    if (curg >= 0) atomicAdd(&d_sums[curg * HID + col], run);
}

// ---------------------------------------------------------------------------
// Final: per-graph mean, 64->2 head, stable log_softmax. Counts via binary
// search on the sorted batch array.
// ---------------------------------------------------------------------------
__global__ void final_kernel(const float* __restrict__ w3, const float* __restrict__ b3,
                             const int* __restrict__ batch, float* __restrict__ out,
                             int n, int G) {
    int g = blockIdx.x * blockDim.x + threadIdx.x;
    if (g >= G) return;
    int lo = 0, hi = n;
    while (lo < hi) { int mid = (lo + hi) >> 1; if (batch[mid] < g) lo = mid + 1; else hi = mid; }
    int a = lo;
    hi = n;
    while (lo < hi) { int mid = (lo + hi) >> 1; if (batch[mid] < g + 1) lo = mid + 1; else hi = mid; }
    int cnt = lo - a;
    float inv = 1.f / fmaxf((float)cnt, 1.f);

    float l0 = b3[0], l1 = b3[1];
    const float* sp = &d_sums[g * HID];
    #pragma unroll
    for (int o = 0; o < HID; o++) {
        float pv = sp[o] * inv;
        l0 = fmaf(pv, w3[2 * o],     l0);
        l1 = fmaf(pv, w3[2 * o + 1], l1);
    }
    float m = fmaxf(l0, l1);
    float lse = m + logf(expf(l0 - m) + expf(l1 - m));
    out[2 * g]     = l0 - lse;
    out[2 * g + 1] = l1 - lse;
}

// ---------------------------------------------------------------------------
extern "C" void kernel_launch(void* const* d_in, const int* in_sizes, int n_in,
                              void* d_out, int out_size) {
    const float* x   = (const float*)d_in[0];
    const float* eps = (const float*)d_in[1];
    const float* w1  = (const float*)d_in[2];
    const float* b1  = (const float*)d_in[3];
    const float* g1  = (const float*)d_in[4];
    const float* be1 = (const float*)d_in[5];
    const float* m1  = (const float*)d_in[6];
    const float* v1  = (const float*)d_in[7];
    const float* w2  = (const float*)d_in[8];
    const float* b2  = (const float*)d_in[9];
    const float* g2  = (const float*)d_in[10];
    const float* be2 = (const float*)d_in[11];
    const float* m2  = (const float*)d_in[12];
    const float* v2  = (const float*)d_in[13];
    const float* w3  = (const float*)d_in[14];
    const float* b3  = (const float*)d_in[15];
    const int*   ei  = (const int*)d_in[16];
    const int*   batch = (const int*)d_in[17];

    int n = in_sizes[0] / 4;
    int E = in_sizes[16] / 2;
    int G = out_size / 2;

    static int smem_set = 0;
    if (!smem_set) {
        cudaFuncSetAttribute(mlp_kernel, cudaFuncAttributeMaxDynamicSharedMemorySize, MLP_SMEM);
        smem_set = 1;
    }

    prep_kernel<<<(G * HID + 255) / 256, 256>>>(w1, b1, g1, be1, m1, v1,
                                                w2, b2, g2, be2, m2, v2, G);
    init_kernel<<<(n + 255) / 256, 256>>>((const float4*)x, eps, n);
    int et = (E + 7) / 8;
    edge_kernel<<<(et + 255) / 256, 256>>>(ei, (const float4*)x, E);
    mlp_kernel<<<(n + 255) / 256, 256, MLP_SMEM>>>(batch, n);
    final_kernel<<<(G + 255) / 256, 256>>>(w3, b3, batch, (float*)d_out, n, G);
}

// round 3
// speedup vs baseline: 1.1087x; 1.0747x over previous
#include <cuda_runtime.h>

#define NMAX 500000
#define GMAX 5000
#define HID 64
#define H1  128

// Scratch (static __device__ per allocation rules)
__device__ float4 d_agg[NMAX];           // (1+eps)*x + sum_{j->i} x_j
__device__ float  d_sums[GMAX * HID];    // per-graph h2 sums
__device__ float  d_W1[H1 * 4];          // folded W1, column-major [j][k]
__device__ float  d_C1[H1];              // folded bias1 (BN folded)
__device__ float  d_Bfrag[32 * 256];     // W2 in per-lane mma fragment order
__device__ float  d_C2[HID];             // folded bias2

__device__ __forceinline__ unsigned f2tf(float f) {
    unsigned r;
    asm("cvt.rna.tf32.f32 %0, %1;" : "=r"(r) : "f"(f));
    return r;
}

__device__ __forceinline__ void red4(float4* p, float4 v) {
    asm volatile("red.global.add.v4.f32 [%0], {%1, %2, %3, %4};"
                 :: "l"(p), "f"(v.x), "f"(v.y), "f"(v.z), "f"(v.w)
                 : "memory");
}

__device__ __forceinline__ void mma_tf32(float* c, unsigned a0, unsigned a1,
                                         unsigned a2, unsigned a3,
                                         unsigned b0, unsigned b1) {
    asm volatile(
        "mma.sync.aligned.m16n8k8.row.col.f32.tf32.tf32.f32 "
        "{%0,%1,%2,%3},{%4,%5,%6,%7},{%8,%9},{%0,%1,%2,%3};"
        : "+f"(c[0]), "+f"(c[1]), "+f"(c[2]), "+f"(c[3])
        : "r"(a0), "r"(a1), "r"(a2), "r"(a3), "r"(b0), "r"(b1));
}

// ---------------------------------------------------------------------------
// Prep: fold BN into weights, pre-swizzle W2 into mma B-fragment order,
// zero pooling accumulators.
// Fragment order per lane l (kc=l&3, grp=l>>2): seq q = s*16 + nt*2 + j
//   value = W2fold[k = 8s + kc + 4j][o = 8nt + grp]
// ---------------------------------------------------------------------------
__global__ void prep_kernel(const float* __restrict__ w1, const float* __restrict__ b1,
                            const float* __restrict__ g1, const float* __restrict__ be1,
                            const float* __restrict__ m1, const float* __restrict__ v1,
                            const float* __restrict__ w2, const float* __restrict__ b2,
                            const float* __restrict__ g2, const float* __restrict__ be2,
                            const float* __restrict__ m2, const float* __restrict__ v2,
                            int G) {
    int idx = blockIdx.x * blockDim.x + threadIdx.x;
    if (idx < G * HID) d_sums[idx] = 0.f;
    if (idx < 32 * 256) {
        int l = idx >> 8, q = idx & 255;
        int kc = l & 3, grp = l >> 2;
        int s = q >> 4, r = q & 15, nt = r >> 1, j = r & 1;
        int k = 8 * s + kc + 4 * j;
        int o = 8 * nt + grp;
        float s2 = g2[o] * rsqrtf(v2[o] + 1e-5f);
        d_Bfrag[idx] = __uint_as_float(f2tf(w2[k * HID + o] * s2));
    }
    if (idx < H1) {
        float s1 = g1[idx] * rsqrtf(v1[idx] + 1e-5f);
        #pragma unroll
        for (int k = 0; k < 4; k++) d_W1[idx * 4 + k] = w1[k * H1 + idx] * s1;
        d_C1[idx] = (b1[idx] - m1[idx]) * s1 + be1[idx];
    }
    if (idx < HID) {
        float s2 = g2[idx] * rsqrtf(v2[idx] + 1e-5f);
        d_C2[idx] = (b2[idx] - m2[idx]) * s2 + be2[idx];
    }
}

// ---------------------------------------------------------------------------
// Init: agg[i] = (1+eps) * x[i]
// ---------------------------------------------------------------------------
__global__ void init_kernel(const float4* __restrict__ x, const float* __restrict__ epsp, int n) {
    int i = blockIdx.x * blockDim.x + threadIdx.x;
    if (i < n) {
        float c = 1.f + *epsp;
        float4 v = x[i];
        v.x *= c; v.y *= c; v.z *= c; v.w *= c;
        d_agg[i] = v;
    }
}

// ---------------------------------------------------------------------------
// Edge scatter: agg[dst] += x[src], one vectorized RED per edge, 8 edges/thread.
// Edge-index stream uses evict-first (.cs) so the 128MB stream doesn't thrash
// x/d_agg (16MB) out of L2; gathers use .cg (L2-only, no L1 fill).
// ---------------------------------------------------------------------------
__global__ void edge_kernel(const int* __restrict__ ei, const float4* __restrict__ x, int E) {
    int t = blockIdx.x * blockDim.x + threadIdx.x;
    int e = t * 8;
    if (e + 7 < E) {
        int4 s0 = __ldcs((const int4*)(ei + e));
        int4 s1 = __ldcs((const int4*)(ei + e + 4));
        int4 d0 = __ldcs((const int4*)(ei + E + e));
        int4 d1 = __ldcs((const int4*)(ei + E + e + 4));
        float4 v0 = __ldcg(x + s0.x);
        float4 v1 = __ldcg(x + s0.y);
        float4 v2 = __ldcg(x + s0.z);
        float4 v3 = __ldcg(x + s0.w);
        float4 v4 = __ldcg(x + s1.x);
        float4 v5 = __ldcg(x + s1.y);
        float4 v6 = __ldcg(x + s1.z);
        float4 v7 = __ldcg(x + s1.w);
        red4(&d_agg[d0.x], v0);
        red4(&d_agg[d0.y], v1);
        red4(&d_agg[d0.z], v2);
        red4(&d_agg[d0.w], v3);
        red4(&d_agg[d1.x], v4);
        red4(&d_agg[d1.y], v5);
        red4(&d_agg[d1.z], v6);
        red4(&d_agg[d1.w], v7);
    } else if (e < E) {
        for (int q = e; q < E; q++) {
            int s = ei[q], d = ei[E + q];
            red4(&d_agg[d], __ldcg(x + s));
        }
    }
}

// ---------------------------------------------------------------------------
// Persistent fused MLP + pool. 256 nodes per tile, 256 threads (8 warps),
// grid = 2*SMs blocks looping over tiles. Weights + pre-swizzled B staged in
// smem ONCE per block. Warp w owns rows [32w,32w+32): two m16 tiles share
// every B fragment (64 conflict-free LDS.128/thread for B).
// Separate smem regions for B and h2 staging (no reload per tile).
// ---------------------------------------------------------------------------
#define SM_BF   (32 * 260)          // B fragments, padded
#define SM_H2   (256 * 66)          // h2 staging, stride 66 (float2-aligned)
#define SM_W1   512                 // 128 float4
#define MLP_SMEM_F (SM_BF + SM_H2 + SM_W1 + 128 + 64 + 256)
#define MLP_SMEM (MLP_SMEM_F * 4)

__global__ void __launch_bounds__(256, 2)
mlp_kernel(const int* __restrict__ batch, int n, int numTiles) {
    extern __shared__ float sm[];
    float*  Bf   = sm;                       // [32][260]
    float*  h2s  = sm + SM_BF;               // [256][66]
    float4* W1s  = (float4*)(sm + SM_BF + SM_H2);
    float*  C1s  = sm + SM_BF + SM_H2 + SM_W1;
    float*  C2s  = C1s + 128;
    int*    batchs = (int*)(C2s + 64);

    int tid = threadIdx.x;
    int lane = tid & 31, warp = tid >> 5;
    int grp = lane >> 2;      // lane / 4
    int kc  = lane & 3;       // lane % 4

    for (int i = tid; i < 32 * 256; i += 256) {
        int l = i >> 8, q = i & 255;
        Bf[l * 260 + q] = d_Bfrag[i];
    }
    if (tid < H1) {
        W1s[tid] = *reinterpret_cast<const float4*>(&d_W1[tid * 4]);
        C1s[tid] = d_C1[tid];
    }
    if (tid < HID) C2s[tid] = d_C2[tid];
    const float4* bptr = (const float4*)(Bf + lane * 260);

    for (int tile = blockIdx.x; tile < numTiles; tile += gridDim.x) {
        int blockStart = tile * 256;
        __syncthreads();   // weights ready (first iter) / prior scan done

        {
            int nd = blockStart + tid;
            batchs[tid] = (nd < n) ? batch[nd] : -1;
        }

        int rbase = blockStart + warp * 32 + grp;
        float4 h0[4];
        #pragma unroll
        for (int t = 0; t < 4; t++) h0[t] = d_agg[min(rbase + t * 8, n - 1)];

        float acc[2][8][4];
        #pragma unroll
        for (int t = 0; t < 2; t++)
            #pragma unroll
            for (int nt = 0; nt < 8; nt++)
                #pragma unroll
                for (int i = 0; i < 4; i++) acc[t][nt][i] = 0.f;

        #pragma unroll
        for (int s = 0; s < 16; s++) {
            int c0 = 8 * s + kc, c1 = c0 + 4;
            float4 wA = W1s[c0]; float cA = C1s[c0];
            float4 wB = W1s[c1]; float cB = C1s[c1];
            unsigned a0[2], a1[2], a2[2], a3[2];
            #pragma unroll
            for (int t = 0; t < 2; t++) {
                float4 hl = h0[2 * t];
                float4 hh = h0[2 * t + 1];
                float uA0 = fmaf(hl.w, wA.w, fmaf(hl.z, wA.z, fmaf(hl.y, wA.y, fmaf(hl.x, wA.x, cA))));
                float uA1 = fmaf(hh.w, wA.w, fmaf(hh.z, wA.z, fmaf(hh.y, wA.y, fmaf(hh.x, wA.x, cA))));
                float uB0 = fmaf(hl.w, wB.w, fmaf(hl.z, wB.z, fmaf(hl.y, wB.y, fmaf(hl.x, wB.x, cB))));
                float uB1 = fmaf(hh.w, wB.w, fmaf(hh.z, wB.z, fmaf(hh.y, wB.y, fmaf(hh.x, wB.x, cB))));
                a0[t] = f2tf(fmaxf(uA0, 0.f));
                a1[t] = f2tf(fmaxf(uA1, 0.f));
                a2[t] = f2tf(fmaxf(uB0, 0.f));
                a3[t] = f2tf(fmaxf(uB1, 0.f));
            }
            #pragma unroll
            for (int np = 0; np < 4; np++) {
                float4 bv = bptr[s * 4 + np];
                unsigned bx = __float_as_uint(bv.x), by = __float_as_uint(bv.y);
                unsigned bz = __float_as_uint(bv.z), bw = __float_as_uint(bv.w);
                #pragma unroll
                for (int t = 0; t < 2; t++) {
                    mma_tf32(acc[t][2 * np],     a0[t], a1[t], a2[t], a3[t], bx, by);
                    mma_tf32(acc[t][2 * np + 1], a0[t], a1[t], a2[t], a3[t], bz, bw);
                }
            }
        }

        // epilogue: bias + relu, float2 stores into h2 staging
        int r0l = warp * 32 + grp;
        #pragma unroll
        for (int t = 0; t < 2; t++) {
            int rl = r0l + 16 * t;
            #pragma unroll
            for (int nt = 0; nt < 8; nt++) {
                int c = nt * 8 + 2 * kc;
                float2 lo = make_float2(fmaxf(acc[t][nt][0] + C2s[c], 0.f),
                                        fmaxf(acc[t][nt][1] + C2s[c + 1], 0.f));
                float2 hi = make_float2(fmaxf(acc[t][nt][2] + C2s[c], 0.f),
                                        fmaxf(acc[t][nt][3] + C2s[c + 1], 0.f));
                *(float2*)&h2s[rl * 66 + c]       = lo;
                *(float2*)&h2s[(rl + 8) * 66 + c] = hi;
            }
        }
        __syncthreads();

        // segmented pooling scan: thread = (column, node-quarter of 64 rows)
        int col = tid & 63, part = tid >> 6;
        float run = 0.f;
        int curg = -1;
        int lnEnd = part * 64 + 64;
        if (blockStart + lnEnd > n) lnEnd = max(n - blockStart, part * 64);
        #pragma unroll 4
        for (int ln = part * 64; ln < lnEnd; ln++) {
            int g = batchs[ln];
            if (g != curg) {
                if (curg >= 0) atomicAdd(&d_sums[curg * HID + col], run);
                run = 0.f;
                curg = g;
            }
            run += h2s[ln * 66 + col];
        }
        if (curg >= 0) atomicAdd(&d_sums[curg * HID + col], run);
    }
}

// ---------------------------------------------------------------------------
// Final: per-graph mean, 64->2 head, stable log_softmax. Counts via binary
// search on the sorted batch array.
// ---------------------------------------------------------------------------
__global__ void final_kernel(const float* __restrict__ w3, const float* __restrict__ b3,
                             const int* __restrict__ batch, float* __restrict__ out,
                             int n, int G) {
    int g = blockIdx.x * blockDim.x + threadIdx.x;
    if (g >= G) return;
    int lo = 0, hi = n;
    while (lo < hi) { int mid = (lo + hi) >> 1; if (batch[mid] < g) lo = mid + 1; else hi = mid; }
    int a = lo;
    hi = n;
    while (lo < hi) { int mid = (lo + hi) >> 1; if (batch[mid] < g + 1) lo = mid + 1; else hi = mid; }
    int cnt = lo - a;
    float inv = 1.f / fmaxf((float)cnt, 1.f);

    float l0 = b3[0], l1 = b3[1];
    const float* sp = &d_sums[g * HID];
    #pragma unroll
    for (int o = 0; o < HID; o++) {
        float pv = sp[o] * inv;
        l0 = fmaf(pv, w3[2 * o],     l0);
        l1 = fmaf(pv, w3[2 * o + 1], l1);
    }
    float m = fmaxf(l0, l1);
    float lse = m + logf(expf(l0 - m) + expf(l1 - m));
    out[2 * g]     = l0 - lse;
    out[2 * g + 1] = l1 - lse;
}

// ---------------------------------------------------------------------------
extern "C" void kernel_launch(void* const* d_in, const int* in_sizes, int n_in,
                              void* d_out, int out_size) {
    const float* x   = (const float*)d_in[0];
    const float* eps = (const float*)d_in[1];
    const float* w1  = (const float*)d_in[2];
    const float* b1  = (const float*)d_in[3];
    const float* g1  = (const float*)d_in[4];
    const float* be1 = (const float*)d_in[5];
    const float* m1  = (const float*)d_in[6];
    const float* v1  = (const float*)d_in[7];
    const float* w2  = (const float*)d_in[8];
    const float* b2  = (const float*)d_in[9];
    const float* g2  = (const float*)d_in[10];
    const float* be2 = (const float*)d_in[11];
    const float* m2  = (const float*)d_in[12];
    const float* v2  = (const float*)d_in[13];
    const float* w3  = (const float*)d_in[14];
    const float* b3  = (const float*)d_in[15];
    const int*   ei  = (const int*)d_in[16];
    const int*   batch = (const int*)d_in[17];

    int n = in_sizes[0] / 4;
    int E = in_sizes[16] / 2;
    int G = out_size / 2;

    static int smem_set = 0;
    if (!smem_set) {
        cudaFuncSetAttribute(mlp_kernel, cudaFuncAttributeMaxDynamicSharedMemorySize, MLP_SMEM);
        smem_set = 1;
    }

    prep_kernel<<<(G * HID + 255) / 256, 256>>>(w1, b1, g1, be1, m1, v1,
                                                w2, b2, g2, be2, m2, v2, G);
    init_kernel<<<(n + 255) / 256, 256>>>((const float4*)x, eps, n);
    int et = (E + 7) / 8;
    edge_kernel<<<(et + 255) / 256, 256>>>(ei, (const float4*)x, E);
    int numTiles = (n + 255) / 256;
    int mlpGrid = 296;                      // 2 CTAs x 148 SMs
    if (mlpGrid > numTiles) mlpGrid = numTiles;
    mlp_kernel<<<mlpGrid, 256, MLP_SMEM>>>(batch, n, numTiles);
    final_kernel<<<(G + 255) / 256, 256>>>(w3, b3, batch, (float*)d_out, n, G);
}

// round 4
// speedup vs baseline: 1.1997x; 1.0821x over previous
#include <cuda_runtime.h>

#define NMAX 500000
#define GMAX 5000
#define HID 64
#define H1  128

// Scratch (static __device__ per allocation rules)
__device__ float4 d_agg[NMAX];           // (1+eps)*x + sum_{j->i} x_j
__device__ float  d_sums[GMAX * HID];    // per-graph h2 sums
__device__ float  d_W1f[32 * 32];        // layer1 B-fragments (W1+bias row), per-lane order
__device__ float  d_Bfrag[32 * 256];     // W2 in per-lane mma fragment order (K-permuted)
__device__ float  d_C2[HID];             // folded bias2

__device__ __forceinline__ unsigned f2tf(float f) {
    unsigned r;
    asm("cvt.rna.tf32.f32 %0, %1;" : "=r"(r) : "f"(f));
    return r;
}

__device__ __forceinline__ void red4(float4* p, float4 v) {
    asm volatile("red.global.add.v4.f32 [%0], {%1, %2, %3, %4};"
                 :: "l"(p), "f"(v.x), "f"(v.y), "f"(v.z), "f"(v.w)
                 : "memory");
}

__device__ __forceinline__ void mma_tf32(float* c, unsigned a0, unsigned a1,
                                         unsigned a2, unsigned a3,
                                         unsigned b0, unsigned b1) {
    asm volatile(
        "mma.sync.aligned.m16n8k8.row.col.f32.tf32.tf32.f32 "
        "{%0,%1,%2,%3},{%4,%5,%6,%7},{%8,%9},{%0,%1,%2,%3};"
        : "+f"(c[0]), "+f"(c[1]), "+f"(c[2]), "+f"(c[3])
        : "r"(a0), "r"(a1), "r"(a2), "r"(a3), "r"(b0), "r"(b1));
}

// ---------------------------------------------------------------------------
// Prep: fold BN into weights.
// Layer1 B-frags (m16n8k8): lane l (kc=l&3, grp=l>>2), q = 2*nt + j:
//   j=0 -> W1fold[k=kc][col=8nt+grp]          (b0: k-slot kc)
//   j=1 -> kc==0 ? C1fold[col] : 0            (b1: k-slot kc+4; bias row k=4)
// Layer2 B-frags with K-permutation sigma(8s + kc-slot) :
//   k-slot kc   <-> logical h1 col 8s+2kc
//   k-slot kc+4 <-> logical h1 col 8s+2kc+1
//   q = s*16 + nt*2 + j, value = W2fold[k = 8s+2kc+j][o = 8nt+grp]
// ---------------------------------------------------------------------------
__global__ void prep_kernel(const float* __restrict__ w1, const float* __restrict__ b1,
                            const float* __restrict__ g1, const float* __restrict__ be1,
                            const float* __restrict__ m1, const float* __restrict__ v1,
                            const float* __restrict__ w2, const float* __restrict__ b2,
                            const float* __restrict__ g2, const float* __restrict__ be2,
                            const float* __restrict__ m2, const float* __restrict__ v2,
                            int G) {
    int idx = blockIdx.x * blockDim.x + threadIdx.x;
    if (idx < G * HID) d_sums[idx] = 0.f;
    if (idx < 32 * 256) {
        int l = idx >> 8, q = idx & 255;
        int kc = l & 3, grp = l >> 2;
        int s = q >> 4, r = q & 15, nt = r >> 1, j = r & 1;
        int k = 8 * s + 2 * kc + j;          // K-permuted
        int o = 8 * nt + grp;
        float s2 = g2[o] * rsqrtf(v2[o] + 1e-5f);
        d_Bfrag[idx] = __uint_as_float(f2tf(w2[k * HID + o] * s2));
    }
    if (idx < 32 * 32) {
        int l = idx >> 5, q = idx & 31;
        int kc = l & 3, grp = l >> 2;
        int nt = q >> 1, j = q & 1;
        int col = 8 * nt + grp;
        float s1 = g1[col] * rsqrtf(v1[col] + 1e-5f);
        float val;
        if (j == 0)       val = w1[kc * H1 + col] * s1;
        else if (kc == 0) val = (b1[col] - m1[col]) * s1 + be1[col];
        else              val = 0.f;
        d_W1f[idx] = __uint_as_float(f2tf(val));
    }
    if (idx < HID) {
        float s2 = g2[idx] * rsqrtf(v2[idx] + 1e-5f);
        d_C2[idx] = (b2[idx] - m2[idx]) * s2 + be2[idx];
    }
}

// ---------------------------------------------------------------------------
// Init: agg[i] = (1+eps) * x[i]
// ---------------------------------------------------------------------------
__global__ void init_kernel(const float4* __restrict__ x, const float* __restrict__ epsp, int n) {
    int i = blockIdx.x * blockDim.x + threadIdx.x;
    if (i < n) {
        float c = 1.f + *epsp;
        float4 v = x[i];
        v.x *= c; v.y *= c; v.z *= c; v.w *= c;
        d_agg[i] = v;
    }
}

// ---------------------------------------------------------------------------
// Edge scatter: agg[dst] += x[src], one vectorized RED per edge, 8 edges/thread.
// ---------------------------------------------------------------------------
__global__ void edge_kernel(const int* __restrict__ ei, const float4* __restrict__ x, int E) {
    int t = blockIdx.x * blockDim.x + threadIdx.x;
    int e = t * 8;
    if (e + 7 < E) {
        int4 s0 = __ldcs((const int4*)(ei + e));
        int4 s1 = __ldcs((const int4*)(ei + e + 4));
        int4 d0 = __ldcs((const int4*)(ei + E + e));
        int4 d1 = __ldcs((const int4*)(ei + E + e + 4));
        float4 v0 = __ldcg(x + s0.x);
        float4 v1 = __ldcg(x + s0.y);
        float4 v2 = __ldcg(x + s0.z);
        float4 v3 = __ldcg(x + s0.w);
        float4 v4 = __ldcg(x + s1.x);
        float4 v5 = __ldcg(x + s1.y);
        float4 v6 = __ldcg(x + s1.z);
        float4 v7 = __ldcg(x + s1.w);
        red4(&d_agg[d0.x], v0);
        red4(&d_agg[d0.y], v1);
        red4(&d_agg[d0.z], v2);
        red4(&d_agg[d0.w], v3);
        red4(&d_agg[d1.x], v4);
        red4(&d_agg[d1.y], v5);
        red4(&d_agg[d1.z], v6);
        red4(&d_agg[d1.w], v7);
    } else if (e < E) {
        for (int q = e; q < E; q++) {
            int s = ei[q], d = ei[E + q];
            red4(&d_agg[d], __ldcg(x + s));
        }
    }
}

// ---------------------------------------------------------------------------
// Persistent fused MLP + pool, all-tensor path.
// Layer1: mma.m16n8k8 with A=[x,1,0,0,0] (bias via K row 4).
// Layer2: mma.m16n8k8 with K-permuted W2 so layer1 acc feeds A-frags with
// ZERO shuffles (a0=relu(c0), a1=relu(c2), a2=relu(c1), a3=relu(c3)).
// Pool: float4 segmented scan + red.v4 flushes.
// ---------------------------------------------------------------------------
#define SM_BF   (32 * 260)          // layer2 B fragments
#define SM_W1   (32 * 34)           // layer1 B fragments
#define SM_H2   (256 * 68)          // h2 staging, stride 68 (16B-aligned rows)
#define MLP_SMEM_F (SM_BF + SM_W1 + SM_H2 + 64 + 256)
#define MLP_SMEM (MLP_SMEM_F * 4)

__global__ void __launch_bounds__(256, 2)
mlp_kernel(const int* __restrict__ batch, int n, int numTiles) {
    extern __shared__ float sm[];
    float*  Bf   = sm;                       // [32][260]
    float*  W1s  = sm + SM_BF;               // [32][34]
    float*  h2s  = sm + SM_BF + SM_W1;       // [256][68]
    float*  C2s  = sm + SM_BF + SM_W1 + SM_H2;
    int*    batchs = (int*)(C2s + 64);

    int tid = threadIdx.x;
    int lane = tid & 31, warp = tid >> 5;
    int grp = lane >> 2;      // lane / 4
    int kc  = lane & 3;       // lane % 4

    for (int i = tid; i < 32 * 256; i += 256) {
        int l = i >> 8, q = i & 255;
        Bf[l * 260 + q] = d_Bfrag[i];
    }
    for (int i = tid; i < 32 * 32; i += 256) {
        int l = i >> 5, q = i & 31;
        W1s[l * 34 + q] = d_W1f[i];
    }
    if (tid < HID) C2s[tid] = d_C2[tid];

    const float4* bptr  = (const float4*)(Bf + lane * 260);
    const float2* w1ptr = (const float2*)(W1s + lane * 34);
    const float*  xs    = (const float*)d_agg;
    unsigned A2 = (kc == 0) ? 0x3F800000u : 0u;   // bias-row A value (tf32 1.0)

    for (int tile = blockIdx.x; tile < numTiles; tile += gridDim.x) {
        int blockStart = tile * 256;
        __syncthreads();   // weights ready (first iter) / prior scan done

        {
            int nd = blockStart + tid;
            batchs[tid] = (nd < n) ? batch[nd] : -1;
        }

        int rb = blockStart + warp * 32 + grp;
        unsigned a0[2], a1[2];
        #pragma unroll
        for (int t = 0; t < 2; t++) {
            a0[t] = f2tf(xs[min(rb + 16 * t,     n - 1) * 4 + kc]);
            a1[t] = f2tf(xs[min(rb + 16 * t + 8, n - 1) * 4 + kc]);
        }

        float acc[2][8][4];
        #pragma unroll
        for (int t = 0; t < 2; t++)
            #pragma unroll
            for (int nt = 0; nt < 8; nt++)
                #pragma unroll
                for (int i = 0; i < 4; i++) acc[t][nt][i] = 0.f;

        #pragma unroll
        for (int s = 0; s < 16; s++) {
            // layer1 mma for h1 col-group s (8 cols)
            float2 bw = w1ptr[s];
            unsigned bb0 = __float_as_uint(bw.x), bb1 = __float_as_uint(bw.y);
            float d1[2][4] = {{0.f,0.f,0.f,0.f},{0.f,0.f,0.f,0.f}};
            mma_tf32(d1[0], a0[0], a1[0], A2, A2, bb0, bb1);
            mma_tf32(d1[1], a0[1], a1[1], A2, A2, bb0, bb1);
            // relu + cvt -> layer2 A-frags (K-permutation makes this direct)
            unsigned f0[2], f1[2], f2v[2], f3[2];
            #pragma unroll
            for (int t = 0; t < 2; t++) {
                f0[t]  = f2tf(fmaxf(d1[t][0], 0.f));
                f2v[t] = f2tf(fmaxf(d1[t][1], 0.f));
                f1[t]  = f2tf(fmaxf(d1[t][2], 0.f));
                f3[t]  = f2tf(fmaxf(d1[t][3], 0.f));
            }
            // layer2: 8 n-tiles
            #pragma unroll
            for (int np = 0; np < 4; np++) {
                float4 bv = bptr[s * 4 + np];
                unsigned bx = __float_as_uint(bv.x), by = __float_as_uint(bv.y);
                unsigned bz = __float_as_uint(bv.z), bwv = __float_as_uint(bv.w);
                #pragma unroll
                for (int t = 0; t < 2; t++) {
                    mma_tf32(acc[t][2 * np],     f0[t], f1[t], f2v[t], f3[t], bx, by);
                    mma_tf32(acc[t][2 * np + 1], f0[t], f1[t], f2v[t], f3[t], bz, bwv);
                }
            }
        }

        // epilogue: bias + relu, float2 stores into h2 staging
        int r0l = warp * 32 + grp;
        #pragma unroll
        for (int t = 0; t < 2; t++) {
            int rl = r0l + 16 * t;
            #pragma unroll
            for (int nt = 0; nt < 8; nt++) {
                int c = nt * 8 + 2 * kc;
                float2 lo = make_float2(fmaxf(acc[t][nt][0] + C2s[c], 0.f),
                                        fmaxf(acc[t][nt][1] + C2s[c + 1], 0.f));
                float2 hi = make_float2(fmaxf(acc[t][nt][2] + C2s[c], 0.f),
                                        fmaxf(acc[t][nt][3] + C2s[c + 1], 0.f));
                *(float2*)&h2s[rl * 68 + c]       = lo;
                *(float2*)&h2s[(rl + 8) * 68 + c] = hi;
            }
        }
        __syncthreads();

        // segmented pooling scan: thread = (4-col group, 16-row part)
        int col4 = (tid & 15) * 4;
        int part = tid >> 4;            // 0..15
        float4 run = make_float4(0.f, 0.f, 0.f, 0.f);
        int curg = -1;
        #pragma unroll 4
        for (int i = 0; i < 16; i++) {
            int ln = part * 16 + i;
            int g = batchs[ln];
            if (g != curg) {
                if (curg >= 0) red4((float4*)&d_sums[curg * HID + col4], run);
                if (g < 0) { curg = -1; break; }
                run = make_float4(0.f, 0.f, 0.f, 0.f);
                curg = g;
            }
            float4 v = *(const float4*)&h2s[ln * 68 + col4];
            run.x += v.x; run.y += v.y; run.z += v.z; run.w += v.w;
        }
        if (curg >= 0) red4((float4*)&d_sums[curg * HID + col4], run);
    }
}

// ---------------------------------------------------------------------------
// Final: per-graph mean, 64->2 head, stable log_softmax.
// ---------------------------------------------------------------------------
__global__ void final_kernel(const float* __restrict__ w3, const float* __restrict__ b3,
                             const int* __restrict__ batch, float* __restrict__ out,
                             int n, int G) {
    int g = blockIdx.x * blockDim.x + threadIdx.x;
    if (g >= G) return;
    int lo = 0, hi = n;
    while (lo < hi) { int mid = (lo + hi) >> 1; if (batch[mid] < g) lo = mid + 1; else hi = mid; }
    int a = lo;
    hi = n;
    while (lo < hi) { int mid = (lo + hi) >> 1; if (batch[mid] < g + 1) lo = mid + 1; else hi = mid; }
    int cnt = lo - a;
    float inv = 1.f / fmaxf((float)cnt, 1.f);

    float l0 = b3[0], l1 = b3[1];
    const float* sp = &d_sums[g * HID];
    #pragma unroll
    for (int o = 0; o < HID; o++) {
        float pv = sp[o] * inv;
        l0 = fmaf(pv, w3[2 * o],     l0);
        l1 = fmaf(pv, w3[2 * o + 1], l1);
    }
    float m = fmaxf(l0, l1);
    float lse = m + logf(expf(l0 - m) + expf(l1 - m));
    out[2 * g]     = l0 - lse;
    out[2 * g + 1] = l1 - lse;
}

// ---------------------------------------------------------------------------
extern "C" void kernel_launch(void* const* d_in, const int* in_sizes, int n_in,
                              void* d_out, int out_size) {
    const float* x   = (const float*)d_in[0];
    const float* eps = (const float*)d_in[1];
    const float* w1  = (const float*)d_in[2];
    const float* b1  = (const float*)d_in[3];
    const float* g1  = (const float*)d_in[4];
    const float* be1 = (const float*)d_in[5];
    const float* m1  = (const float*)d_in[6];
    const float* v1  = (const float*)d_in[7];
    const float* w2  = (const float*)d_in[8];
    const float* b2  = (const float*)d_in[9];
    const float* g2  = (const float*)d_in[10];
    const float* be2 = (const float*)d_in[11];
    const float* m2  = (const float*)d_in[12];
    const float* v2  = (const float*)d_in[13];
    const float* w3  = (const float*)d_in[14];
    const float* b3  = (const float*)d_in[15];
    const int*   ei  = (const int*)d_in[16];
    const int*   batch = (const int*)d_in[17];

    int n = in_sizes[0] / 4;
    int E = in_sizes[16] / 2;
    int G = out_size / 2;

    static int smem_set = 0;
    if (!smem_set) {
        cudaFuncSetAttribute(mlp_kernel, cudaFuncAttributeMaxDynamicSharedMemorySize, MLP_SMEM);
        smem_set = 1;
    }

    prep_kernel<<<(G * HID + 255) / 256, 256>>>(w1, b1, g1, be1, m1, v1,
                                                w2, b2, g2, be2, m2, v2, G);
    init_kernel<<<(n + 255) / 256, 256>>>((const float4*)x, eps, n);
    int et = (E + 7) / 8;
    edge_kernel<<<(et + 255) / 256, 256>>>(ei, (const float4*)x, E);
    int numTiles = (n + 255) / 256;
    int mlpGrid = 296;                      // 2 CTAs x 148 SMs
    if (mlpGrid > numTiles) mlpGrid = numTiles;
    mlp_kernel<<<mlpGrid, 256, MLP_SMEM>>>(batch, n, numTiles);
    final_kernel<<<(G + 255) / 256, 256>>>(w3, b3, batch, (float*)d_out, n, G);
}

// round 5
// speedup vs baseline: 1.2248x; 1.0209x over previous
#include <cuda_runtime.h>

#define NMAX 500000
#define GMAX 5000
#define HID 64
#define H1  128

// Scratch (static __device__ per allocation rules)
__device__ float4 d_agg[NMAX];           // (1+eps)*x + sum_{j->i} x_j
__device__ float  d_sums[GMAX * HID];    // per-graph h2 sums
__device__ float  d_W1f[32 * 32];        // layer1 B-fragments (W1+bias row), per-lane order
__device__ float  d_Bfrag[32 * 256];     // W2 in per-lane mma fragment order (K-permuted)
__device__ float  d_C2[HID];             // folded bias2

__device__ __forceinline__ unsigned f2tf(float f) {
    unsigned r;
    asm("cvt.rna.tf32.f32 %0, %1;" : "=r"(r) : "f"(f));
    return r;
}

__device__ __forceinline__ void red4(float4* p, float4 v) {
    asm volatile("red.global.add.v4.f32 [%0], {%1, %2, %3, %4};"
                 :: "l"(p), "f"(v.x), "f"(v.y), "f"(v.z), "f"(v.w)
                 : "memory");
}

__device__ __forceinline__ void mma_tf32(float* c, unsigned a0, unsigned a1,
                                         unsigned a2, unsigned a3,
                                         unsigned b0, unsigned b1) {
    asm volatile(
        "mma.sync.aligned.m16n8k8.row.col.f32.tf32.tf32.f32 "
        "{%0,%1,%2,%3},{%4,%5,%6,%7},{%8,%9},{%0,%1,%2,%3};"
        : "+f"(c[0]), "+f"(c[1]), "+f"(c[2]), "+f"(c[3])
        : "r"(a0), "r"(a1), "r"(a2), "r"(a3), "r"(b0), "r"(b1));
}

// ---------------------------------------------------------------------------
// Prep: fold BN into weights.
// Layer1 B-frags (m16n8k8): lane l (kc=l&3, grp=l>>2), q = 2*nt + j:
//   j=0 -> W1fold[k=kc][col=8nt+grp]          (b0: k-slot kc)
//   j=1 -> kc==0 ? C1fold[col] : 0            (b1: k-slot kc+4; bias row k=4)
// Layer2 B-frags with K-permutation:
//   q = s*16 + nt*2 + j, value = W2fold[k = 8s+2kc+j][o = 8nt+grp]
// ---------------------------------------------------------------------------
__global__ void prep_kernel(const float* __restrict__ w1, const float* __restrict__ b1,
                            const float* __restrict__ g1, const float* __restrict__ be1,
                            const float* __restrict__ m1, const float* __restrict__ v1,
                            const float* __restrict__ w2, const float* __restrict__ b2,
                            const float* __restrict__ g2, const float* __restrict__ be2,
                            const float* __restrict__ m2, const float* __restrict__ v2,
                            int G) {
    int idx = blockIdx.x * blockDim.x + threadIdx.x;
    if (idx < G * HID) d_sums[idx] = 0.f;
    if (idx < 32 * 256) {
        int l = idx >> 8, q = idx & 255;
        int kc = l & 3, grp = l >> 2;
        int s = q >> 4, r = q & 15, nt = r >> 1, j = r & 1;
        int k = 8 * s + 2 * kc + j;          // K-permuted
        int o = 8 * nt + grp;
        float s2 = g2[o] * rsqrtf(v2[o] + 1e-5f);
        d_Bfrag[idx] = __uint_as_float(f2tf(w2[k * HID + o] * s2));
    }
    if (idx < 32 * 32) {
        int l = idx >> 5, q = idx & 31;
        int kc = l & 3, grp = l >> 2;
        int nt = q >> 1, j = q & 1;
        int col = 8 * nt + grp;
        float s1 = g1[col] * rsqrtf(v1[col] + 1e-5f);
        float val;
        if (j == 0)       val = w1[kc * H1 + col] * s1;
        else if (kc == 0) val = (b1[col] - m1[col]) * s1 + be1[col];
        else              val = 0.f;
        d_W1f[idx] = __uint_as_float(f2tf(val));
    }
    if (idx < HID) {
        float s2 = g2[idx] * rsqrtf(v2[idx] + 1e-5f);
        d_C2[idx] = (b2[idx] - m2[idx]) * s2 + be2[idx];
    }
}

// ---------------------------------------------------------------------------
// Init: agg[i] = (1+eps) * x[i]
// ---------------------------------------------------------------------------
__global__ void init_kernel(const float4* __restrict__ x, const float* __restrict__ epsp, int n) {
    int i = blockIdx.x * blockDim.x + threadIdx.x;
    if (i < n) {
        float c = 1.f + *epsp;
        float4 v = x[i];
        v.x *= c; v.y *= c; v.z *= c; v.w *= c;
        d_agg[i] = v;
    }
}

// ---------------------------------------------------------------------------
// Edge scatter: agg[dst] += x[src], one vectorized RED per edge, 8 edges/thread.
// Index stream evict-first (.cs); gathers via __ldg (L1-allocate — no other L1
// traffic in this kernel, so L1 hits shave LTS sectors).
// ---------------------------------------------------------------------------
__global__ void edge_kernel(const int* __restrict__ ei, const float4* __restrict__ x, int E) {
    int t = blockIdx.x * blockDim.x + threadIdx.x;
    int e = t * 8;
    if (e + 7 < E) {
        int4 s0 = __ldcs((const int4*)(ei + e));
        int4 s1 = __ldcs((const int4*)(ei + e + 4));
        int4 d0 = __ldcs((const int4*)(ei + E + e));
        int4 d1 = __ldcs((const int4*)(ei + E + e + 4));
        float4 v0 = __ldg(x + s0.x);
        float4 v1 = __ldg(x + s0.y);
        float4 v2 = __ldg(x + s0.z);
        float4 v3 = __ldg(x + s0.w);
        float4 v4 = __ldg(x + s1.x);
        float4 v5 = __ldg(x + s1.y);
        float4 v6 = __ldg(x + s1.z);
        float4 v7 = __ldg(x + s1.w);
        red4(&d_agg[d0.x], v0);
        red4(&d_agg[d0.y], v1);
        red4(&d_agg[d0.z], v2);
        red4(&d_agg[d0.w], v3);
        red4(&d_agg[d1.x], v4);
        red4(&d_agg[d1.y], v5);
        red4(&d_agg[d1.z], v6);
        red4(&d_agg[d1.w], v7);
    } else if (e < E) {
        for (int q = e; q < E; q++) {
            int s = ei[q], d = ei[E + q];
            red4(&d_agg[d], __ldg(x + s));
        }
    }
}

// ---------------------------------------------------------------------------
// Persistent fused MLP + pool, all-tensor path, software-pipelined across
// tiles: next tile's A-fragments + batch ids prefetched into registers during
// the current tile's mma phase (LDG latency hidden behind ~10k cycles of mma).
// Layer1->layer2 hand-off uses raw f32 bits as tf32 (HW truncation, no cvt).
// ---------------------------------------------------------------------------
#define SM_BF   (32 * 260)          // layer2 B fragments
#define SM_W1   (32 * 34)           // layer1 B fragments
#define SM_H2   (256 * 68)          // h2 staging, stride 68 (16B-aligned rows)
#define MLP_SMEM_F (SM_BF + SM_W1 + SM_H2 + 64 + 256)
#define MLP_SMEM (MLP_SMEM_F * 4)

__global__ void __launch_bounds__(256, 2)
mlp_kernel(const int* __restrict__ batch, int n, int numTiles) {
    extern __shared__ float sm[];
    float*  Bf   = sm;                       // [32][260]
    float*  W1s  = sm + SM_BF;               // [32][34]
    float*  h2s  = sm + SM_BF + SM_W1;       // [256][68]
    float*  C2s  = sm + SM_BF + SM_W1 + SM_H2;
    int*    batchs = (int*)(C2s + 64);

    int tid = threadIdx.x;
    int lane = tid & 31, warp = tid >> 5;
    int grp = lane >> 2;      // lane / 4
    int kc  = lane & 3;       // lane % 4

    for (int i = tid; i < 32 * 256; i += 256) {
        int l = i >> 8, q = i & 255;
        Bf[l * 260 + q] = d_Bfrag[i];
    }
    for (int i = tid; i < 32 * 32; i += 256) {
        int l = i >> 5, q = i & 31;
        W1s[l * 34 + q] = d_W1f[i];
    }
    if (tid < HID) C2s[tid] = d_C2[tid];

    const float4* bptr  = (const float4*)(Bf + lane * 260);
    const float2* w1ptr = (const float2*)(W1s + lane * 34);
    const float*  xs    = (const float*)d_agg;
    unsigned A2 = (kc == 0) ? 0x3F800000u : 0u;   // bias-row A value (tf32 1.0)

    // prologue prefetch for first tile
    float pv[4];
    int   pb;
    {
        int tile0 = blockIdx.x;
        int rb = tile0 * 256 + warp * 32 + grp;
        #pragma unroll
        for (int t = 0; t < 4; t++) pv[t] = xs[min(rb + 8 * t, n - 1) * 4 + kc];
        int nd = tile0 * 256 + tid;
        pb = (nd < n) ? batch[nd] : -1;
    }

    for (int tile = blockIdx.x; tile < numTiles; tile += gridDim.x) {
        int blockStart = tile * 256;
        __syncthreads();   // weights ready (first iter) / prior scan done

        batchs[tid] = pb;

        unsigned a0[2], a1[2];
        a0[0] = f2tf(pv[0]); a1[0] = f2tf(pv[1]);
        a0[1] = f2tf(pv[2]); a1[1] = f2tf(pv[3]);

        // issue prefetch for the NEXT tile now; consumed after this tile's work
        {
            int tile2 = tile + gridDim.x;
            int tc = min(tile2, numTiles - 1);
            int rb = tc * 256 + warp * 32 + grp;
            #pragma unroll
            for (int t = 0; t < 4; t++) pv[t] = xs[min(rb + 8 * t, n - 1) * 4 + kc];
            int nd = tile2 * 256 + tid;
            pb = (tile2 < numTiles && nd < n) ? batch[min(nd, n - 1)] : -1;
        }

        float acc[2][8][4];
        #pragma unroll
        for (int t = 0; t < 2; t++)
            #pragma unroll
            for (int nt = 0; nt < 8; nt++)
                #pragma unroll
                for (int i = 0; i < 4; i++) acc[t][nt][i] = 0.f;

        #pragma unroll
        for (int s = 0; s < 16; s++) {
            // layer1 mma for h1 col-group s (8 cols)
            float2 bw = w1ptr[s];
            unsigned bb0 = __float_as_uint(bw.x), bb1 = __float_as_uint(bw.y);
            float d1[2][4] = {{0.f,0.f,0.f,0.f},{0.f,0.f,0.f,0.f}};
            mma_tf32(d1[0], a0[0], a1[0], A2, A2, bb0, bb1);
            mma_tf32(d1[1], a0[1], a1[1], A2, A2, bb0, bb1);
            // relu -> layer2 A-frags; raw f32 bits act as truncated tf32
            unsigned f0[2], f1[2], f2v[2], f3[2];
            #pragma unroll
            for (int t = 0; t < 2; t++) {
                f0[t]  = __float_as_uint(fmaxf(d1[t][0], 0.f));
                f2v[t] = __float_as_uint(fmaxf(d1[t][1], 0.f));
                f1[t]  = __float_as_uint(fmaxf(d1[t][2], 0.f));
                f3[t]  = __float_as_uint(fmaxf(d1[t][3], 0.f));
            }
            // layer2: 8 n-tiles
            #pragma unroll
            for (int np = 0; np < 4; np++) {
                float4 bv = bptr[s * 4 + np];
                unsigned bx = __float_as_uint(bv.x), by = __float_as_uint(bv.y);
                unsigned bz = __float_as_uint(bv.z), bwv = __float_as_uint(bv.w);
                #pragma unroll
                for (int t = 0; t < 2; t++) {
                    mma_tf32(acc[t][2 * np],     f0[t], f1[t], f2v[t], f3[t], bx, by);
                    mma_tf32(acc[t][2 * np + 1], f0[t], f1[t], f2v[t], f3[t], bz, bwv);
                }
            }
        }

        // epilogue: bias + relu, float2 stores into h2 staging
        int r0l = warp * 32 + grp;
        #pragma unroll
        for (int t = 0; t < 2; t++) {
            int rl = r0l + 16 * t;
            #pragma unroll
            for (int nt = 0; nt < 8; nt++) {
                int c = nt * 8 + 2 * kc;
                float2 lo = make_float2(fmaxf(acc[t][nt][0] + C2s[c], 0.f),
                                        fmaxf(acc[t][nt][1] + C2s[c + 1], 0.f));
                float2 hi = make_float2(fmaxf(acc[t][nt][2] + C2s[c], 0.f),
                                        fmaxf(acc[t][nt][3] + C2s[c + 1], 0.f));
                *(float2*)&h2s[rl * 68 + c]       = lo;
                *(float2*)&h2s[(rl + 8) * 68 + c] = hi;
            }
        }
        __syncthreads();

        // segmented pooling scan: thread = (4-col group, 16-row part)
        int col4 = (tid & 15) * 4;
        int part = tid >> 4;            // 0..15
        float4 run = make_float4(0.f, 0.f, 0.f, 0.f);
        int curg = -1;
        #pragma unroll 4
        for (int i = 0; i < 16; i++) {
            int ln = part * 16 + i;
            int g = batchs[ln];
            if (g != curg) {
                if (curg >= 0) red4((float4*)&d_sums[curg * HID + col4], run);
                if (g < 0) { curg = -1; break; }
                run = make_float4(0.f, 0.f, 0.f, 0.f);
                curg = g;
            }
            float4 v = *(const float4*)&h2s[ln * 68 + col4];
            run.x += v.x; run.y += v.y; run.z += v.z; run.w += v.w;
        }
        if (curg >= 0) red4((float4*)&d_sums[curg * HID + col4], run);
    }
}

// ---------------------------------------------------------------------------
// Final: per-graph mean, 64->2 head, stable log_softmax.
// ---------------------------------------------------------------------------
__global__ void final_kernel(const float* __restrict__ w3, const float* __restrict__ b3,
                             const int* __restrict__ batch, float* __restrict__ out,
                             int n, int G) {
    int g = blockIdx.x * blockDim.x + threadIdx.x;
    if (g >= G) return;
    int lo = 0, hi = n;
    while (lo < hi) { int mid = (lo + hi) >> 1; if (batch[mid] < g) lo = mid + 1; else hi = mid; }
    int a = lo;
    hi = n;
    while (lo < hi) { int mid = (lo + hi) >> 1; if (batch[mid] < g + 1) lo = mid + 1; else hi = mid; }
    int cnt = lo - a;
    float inv = 1.f / fmaxf((float)cnt, 1.f);

    float l0 = b3[0], l1 = b3[1];
    const float* sp = &d_sums[g * HID];
    #pragma unroll
    for (int o = 0; o < HID; o++) {
        float pv = sp[o] * inv;
        l0 = fmaf(pv, w3[2 * o],     l0);
        l1 = fmaf(pv, w3[2 * o + 1], l1);
    }
    float m = fmaxf(l0, l1);
    float lse = m + logf(expf(l0 - m) + expf(l1 - m));
    out[2 * g]     = l0 - lse;
    out[2 * g + 1] = l1 - lse;
}

// ---------------------------------------------------------------------------
extern "C" void kernel_launch(void* const* d_in, const int* in_sizes, int n_in,
                              void* d_out, int out_size) {
    const float* x   = (const float*)d_in[0];
    const float* eps = (const float*)d_in[1];
    const float* w1  = (const float*)d_in[2];
    const float* b1  = (const float*)d_in[3];
    const float* g1  = (const float*)d_in[4];
    const float* be1 = (const float*)d_in[5];
    const float* m1  = (const float*)d_in[6];
    const float* v1  = (const float*)d_in[7];
    const float* w2  = (const float*)d_in[8];
    const float* b2  = (const float*)d_in[9];
    const float* g2  = (const float*)d_in[10];
    const float* be2 = (const float*)d_in[11];
    const float* m2  = (const float*)d_in[12];
    const float* v2  = (const float*)d_in[13];
    const float* w3  = (const float*)d_in[14];
    const float* b3  = (const float*)d_in[15];
    const int*   ei  = (const int*)d_in[16];
    const int*   batch = (const int*)d_in[17];

    int n = in_sizes[0] / 4;
    int E = in_sizes[16] / 2;
    int G = out_size / 2;

    static int smem_set = 0;
    if (!smem_set) {
        cudaFuncSetAttribute(mlp_kernel, cudaFuncAttributeMaxDynamicSharedMemorySize, MLP_SMEM);
        smem_set = 1;
    }

    prep_kernel<<<(G * HID + 255) / 256, 256>>>(w1, b1, g1, be1, m1, v1,
                                                w2, b2, g2, be2, m2, v2, G);
    init_kernel<<<(n + 255) / 256, 256>>>((const float4*)x, eps, n);
    int et = (E + 7) / 8;
    edge_kernel<<<(et + 255) / 256, 256>>>(ei, (const float4*)x, E);
    int numTiles = (n + 255) / 256;
    int mlpGrid = 296;                      // 2 CTAs x 148 SMs
    if (mlpGrid > numTiles) mlpGrid = numTiles;
    mlp_kernel<<<mlpGrid, 256, MLP_SMEM>>>(batch, n, numTiles);
    final_kernel<<<(G + 255) / 256, 256>>>(w3, b3, batch, (float*)d_out, n, G);
}

// round 7
// speedup vs baseline: 1.2720x; 1.0385x over previous
#include <cuda_runtime.h>

#define NMAX 500000
#define GMAX 5000
#define HID 64
#define H1  128

// Scratch (static __device__ per allocation rules)
__device__ float4 d_agg[NMAX];           // (1+eps)*x + sum_{j->i} x_j
__device__ float  d_sums[GMAX * HID];    // per-graph h2 sums
__device__ float  d_cnt[GMAX];           // per-graph node counts (as float)
__device__ float  d_W1f[32 * 32];        // layer1 B-fragments (W1+bias row), per-lane order
__device__ float  d_Bfrag[32 * 256];     // W2 in per-lane mma fragment order (K-permuted)
__device__ float  d_C2[HID];             // folded bias2

__device__ __forceinline__ unsigned f2tf(float f) {
    unsigned r;
    asm("cvt.rna.tf32.f32 %0, %1;" : "=r"(r) : "f"(f));
    return r;
}

__device__ __forceinline__ void red4(float4* p, float4 v) {
    asm volatile("red.global.add.v4.f32 [%0], {%1, %2, %3, %4};"
                 :: "l"(p), "f"(v.x), "f"(v.y), "f"(v.z), "f"(v.w)
                 : "memory");
}

__device__ __forceinline__ void redf(float* p, float v) {
    asm volatile("red.global.add.f32 [%0], %1;" :: "l"(p), "f"(v) : "memory");
}

__device__ __forceinline__ void mma_tf32(float* c, unsigned a0, unsigned a1,
                                         unsigned a2, unsigned a3,
                                         unsigned b0, unsigned b1) {
    asm volatile(
        "mma.sync.aligned.m16n8k8.row.col.f32.tf32.tf32.f32 "
        "{%0,%1,%2,%3},{%4,%5,%6,%7},{%8,%9},{%0,%1,%2,%3};"
        : "+f"(c[0]), "+f"(c[1]), "+f"(c[2]), "+f"(c[3])
        : "r"(a0), "r"(a1), "r"(a2), "r"(a3), "r"(b0), "r"(b1));
}

// ---------------------------------------------------------------------------
// Merged prep + init: fold BN into weights (low blocks) AND initialize
// agg[i] = (1+eps)*x[i] (all blocks). Zero pooling accumulators + counts.
// Layer1 B-frags (m16n8k8): lane l (kc=l&3, grp=l>>2), q = 2*nt + j:
//   j=0 -> W1fold[k=kc][col=8nt+grp]      j=1 -> kc==0 ? C1fold[col] : 0
// Layer2 B-frags with K-permutation: q=s*16+nt*2+j,
//   value = W2fold[k = 8s+2kc+j][o = 8nt+grp]
// ---------------------------------------------------------------------------
__global__ void prep_init_kernel(const float4* __restrict__ x, const float* __restrict__ epsp,
                            const float* __restrict__ w1, const float* __restrict__ b1,
                            const float* __restrict__ g1, const float* __restrict__ be1,
                            const float* __restrict__ m1, const float* __restrict__ v1,
                            const float* __restrict__ w2, const float* __restrict__ b2,
                            const float* __restrict__ g2, const float* __restrict__ be2,
                            const float* __restrict__ m2, const float* __restrict__ v2,
                            int n, int G) {
    int idx = blockIdx.x * blockDim.x + threadIdx.x;
    if (idx < n) {
        float c = 1.f + *epsp;
        float4 v = x[idx];
        v.x *= c; v.y *= c; v.z *= c; v.w *= c;
        d_agg[idx] = v;
    }
    if (idx < G * HID) d_sums[idx] = 0.f;
    if (idx < G) d_cnt[idx] = 0.f;
    if (idx < 32 * 256) {
        int l = idx >> 8, q = idx & 255;
        int kc = l & 3, grp = l >> 2;
        int s = q >> 4, r = q & 15, nt = r >> 1, j = r & 1;
        int k = 8 * s + 2 * kc + j;          // K-permuted
        int o = 8 * nt + grp;
        float s2 = g2[o] * rsqrtf(v2[o] + 1e-5f);
        d_Bfrag[idx] = __uint_as_float(f2tf(w2[k * HID + o] * s2));
    }
    if (idx < 32 * 32) {
        int l = idx >> 5, q = idx & 31;
        int kc = l & 3, grp = l >> 2;
        int nt = q >> 1, j = q & 1;
        int col = 8 * nt + grp;
        float s1 = g1[col] * rsqrtf(v1[col] + 1e-5f);
        float val;
        if (j == 0)       val = w1[kc * H1 + col] * s1;
        else if (kc == 0) val = (b1[col] - m1[col]) * s1 + be1[col];
        else              val = 0.f;
        d_W1f[idx] = __uint_as_float(f2tf(val));
    }
    if (idx < HID) {
        float s2 = g2[idx] * rsqrtf(v2[idx] + 1e-5f);
        d_C2[idx] = (b2[idx] - m2[idx]) * s2 + be2[idx];
    }
}

// ---------------------------------------------------------------------------
// Edge scatter: agg[dst] += x[src], one vectorized RED per edge, 8 edges/thread.
// Index stream evict-first (.cs); gathers via __ldg.
// ---------------------------------------------------------------------------
__global__ void edge_kernel(const int* __restrict__ ei, const float4* __restrict__ x, int E) {
    int t = blockIdx.x * blockDim.x + threadIdx.x;
    int e = t * 8;
    if (e + 7 < E) {
        int4 s0 = __ldcs((const int4*)(ei + e));
        int4 s1 = __ldcs((const int4*)(ei + e + 4));
        int4 d0 = __ldcs((const int4*)(ei + E + e));
        int4 d1 = __ldcs((const int4*)(ei + E + e + 4));
        float4 v0 = __ldg(x + s0.x);
        float4 v1 = __ldg(x + s0.y);
        float4 v2 = __ldg(x + s0.z);
        float4 v3 = __ldg(x + s0.w);
        float4 v4 = __ldg(x + s1.x);
        float4 v5 = __ldg(x + s1.y);
        float4 v6 = __ldg(x + s1.z);
        float4 v7 = __ldg(x + s1.w);
        red4(&d_agg[d0.x], v0);
        red4(&d_agg[d0.y], v1);
        red4(&d_agg[d0.z], v2);
        red4(&d_agg[d0.w], v3);
        red4(&d_agg[d1.x], v4);
        red4(&d_agg[d1.y], v5);
        red4(&d_agg[d1.z], v6);
        red4(&d_agg[d1.w], v7);
    } else if (e < E) {
        for (int q = e; q < E; q++) {
            int s = ei[q], d = ei[E + q];
            red4(&d_agg[d], __ldg(x + s));
        }
    }
}

// ---------------------------------------------------------------------------
// Persistent fused MLP + pool, all-tensor path, software-pipelined across
// tiles. Pooling scan also accumulates per-graph node counts (col-leader
// threads), removing the binary searches from the final kernel.
// ---------------------------------------------------------------------------
#define SM_BF   (32 * 260)          // layer2 B fragments
#define SM_W1   (32 * 34)           // layer1 B fragments
#define SM_H2   (256 * 68)          // h2 staging, stride 68 (16B-aligned rows)
#define MLP_SMEM_F (SM_BF + SM_W1 + SM_H2 + 64 + 256)
#define MLP_SMEM (MLP_SMEM_F * 4)

__global__ void __launch_bounds__(256, 2)
mlp_kernel(const int* __restrict__ batch, int n, int numTiles) {
    extern __shared__ float sm[];
    float*  Bf   = sm;                       // [32][260]
    float*  W1s  = sm + SM_BF;               // [32][34]
    float*  h2s  = sm + SM_BF + SM_W1;       // [256][68]
    float*  C2s  = sm + SM_BF + SM_W1 + SM_H2;
    int*    batchs = (int*)(C2s + 64);

    int tid = threadIdx.x;
    int lane = tid & 31, warp = tid >> 5;
    int grp = lane >> 2;      // lane / 4
    int kc  = lane & 3;       // lane % 4

    for (int i = tid; i < 32 * 256; i += 256) {
        int l = i >> 8, q = i & 255;
        Bf[l * 260 + q] = d_Bfrag[i];
    }
    for (int i = tid; i < 32 * 32; i += 256) {
        int l = i >> 5, q = i & 31;
        W1s[l * 34 + q] = d_W1f[i];
    }
    if (tid < HID) C2s[tid] = d_C2[tid];

    const float4* bptr  = (const float4*)(Bf + lane * 260);
    const float2* w1ptr = (const float2*)(W1s + lane * 34);
    const float*  xs    = (const float*)d_agg;
    unsigned A2 = (kc == 0) ? 0x3F800000u : 0u;   // bias-row A value (tf32 1.0)

    // prologue prefetch for first tile
    float pv[4];
    int   pb;
    {
        int tile0 = blockIdx.x;
        int rb = tile0 * 256 + warp * 32 + grp;
        #pragma unroll
        for (int t = 0; t < 4; t++) pv[t] = xs[min(rb + 8 * t, n - 1) * 4 + kc];
        int nd = tile0 * 256 + tid;
        pb = (nd < n) ? batch[nd] : -1;
    }

    for (int tile = blockIdx.x; tile < numTiles; tile += gridDim.x) {
        __syncthreads();   // weights ready (first iter) / prior scan done

        batchs[tid] = pb;

        unsigned a0[2], a1[2];
        a0[0] = f2tf(pv[0]); a1[0] = f2tf(pv[1]);
        a0[1] = f2tf(pv[2]); a1[1] = f2tf(pv[3]);

        // issue prefetch for the NEXT tile now; consumed after this tile's work
        {
            int tile2 = tile + gridDim.x;
            int tc = min(tile2, numTiles - 1);
            int rb = tc * 256 + warp * 32 + grp;
            #pragma unroll
            for (int t = 0; t < 4; t++) pv[t] = xs[min(rb + 8 * t, n - 1) * 4 + kc];
            int nd = tile2 * 256 + tid;
            pb = (tile2 < numTiles && nd < n) ? batch[min(nd, n - 1)] : -1;
        }

        float acc[2][8][4];
        #pragma unroll
        for (int t = 0; t < 2; t++)
            #pragma unroll
            for (int nt = 0; nt < 8; nt++)
                #pragma unroll
                for (int i = 0; i < 4; i++) acc[t][nt][i] = 0.f;

        #pragma unroll
        for (int s = 0; s < 16; s++) {
            // layer1 mma for h1 col-group s (8 cols)
            float2 bw = w1ptr[s];
            unsigned bb0 = __float_as_uint(bw.x), bb1 = __float_as_uint(bw.y);
            float d1[2][4] = {{0.f,0.f,0.f,0.f},{0.f,0.f,0.f,0.f}};
            mma_tf32(d1[0], a0[0], a1[0], A2, A2, bb0, bb1);
            mma_tf32(d1[1], a0[1], a1[1], A2, A2, bb0, bb1);
            // relu -> layer2 A-frags; raw f32 bits act as truncated tf32
            unsigned f0[2], f1[2], f2v[2], f3[2];
            #pragma unroll
            for (int t = 0; t < 2; t++) {
                f0[t]  = __float_as_uint(fmaxf(d1[t][0], 0.f));
                f2v[t] = __float_as_uint(fmaxf(d1[t][1], 0.f));
                f1[t]  = __float_as_uint(fmaxf(d1[t][2], 0.f));
                f3[t]  = __float_as_uint(fmaxf(d1[t][3], 0.f));
            }
            // layer2: 8 n-tiles
            #pragma unroll
            for (int np = 0; np < 4; np++) {
                float4 bv = bptr[s * 4 + np];
                unsigned bx = __float_as_uint(bv.x), by = __float_as_uint(bv.y);
                unsigned bz = __float_as_uint(bv.z), bwv = __float_as_uint(bv.w);
                #pragma unroll
                for (int t = 0; t < 2; t++) {
                    mma_tf32(acc[t][2 * np],     f0[t], f1[t], f2v[t], f3[t], bx, by);
                    mma_tf32(acc[t][2 * np + 1], f0[t], f1[t], f2v[t], f3[t], bz, bwv);
                }
            }
        }

        // epilogue: bias + relu, float2 stores into h2 staging
        int r0l = warp * 32 + grp;
        #pragma unroll
        for (int t = 0; t < 2; t++) {
            int rl = r0l + 16 * t;
            #pragma unroll
            for (int nt = 0; nt < 8; nt++) {
                int c = nt * 8 + 2 * kc;
                float2 lo = make_float2(fmaxf(acc[t][nt][0] + C2s[c], 0.f),
                                        fmaxf(acc[t][nt][1] + C2s[c + 1], 0.f));
                float2 hi = make_float2(fmaxf(acc[t][nt][2] + C2s[c], 0.f),
                                        fmaxf(acc[t][nt][3] + C2s[c + 1], 0.f));
                *(float2*)&h2s[rl * 68 + c]       = lo;
                *(float2*)&h2s[(rl + 8) * 68 + c] = hi;
            }
        }
        __syncthreads();

        // segmented pooling scan: thread = (4-col group, 16-row part).
        // Col-leader threads also accumulate per-graph node counts.
        int col4 = (tid & 15) * 4;
        int part = tid >> 4;            // 0..15
        bool leader = (tid & 15) == 0;
        float4 run = make_float4(0.f, 0.f, 0.f, 0.f);
        float cnt = 0.f;
        int curg = -1;
        #pragma unroll
        for (int i = 0; i < 16; i++) {
            int ln = part * 16 + i;
            int g = batchs[ln];
            if (g != curg) {
                if (curg >= 0) {
                    red4((float4*)&d_sums[curg * HID + col4], run);
                    if (leader) redf(&d_cnt[curg], cnt);
                }
                if (g < 0) { curg = -1; break; }
                run = make_float4(0.f, 0.f, 0.f, 0.f);
                cnt = 0.f;
                curg = g;
            }
            float4 v = *(const float4*)&h2s[ln * 68 + col4];
            run.x += v.x; run.y += v.y; run.z += v.z; run.w += v.w;
            cnt += 1.f;
        }
        if (curg >= 0) {
            red4((float4*)&d_sums[curg * HID + col4], run);
            if (leader) redf(&d_cnt[curg], cnt);
        }
    }
}

// ---------------------------------------------------------------------------
// Final: per-graph mean (counts precomputed), 64->2 head, stable log_softmax.
// ---------------------------------------------------------------------------
__global__ void final_kernel(const float* __restrict__ w3, const float* __restrict__ b3,
                             float* __restrict__ out, int G) {
    int g = blockIdx.x * blockDim.x + threadIdx.x;
    if (g >= G) return;
    float inv = 1.f / fmaxf(d_cnt[g], 1.f);

    float l0 = b3[0], l1 = b3[1];
    const float* sp = &d_sums[g * HID];
    #pragma unroll
    for (int o = 0; o < HID; o++) {
        float pv = sp[o] * inv;
        l0 = fmaf(pv, w3[2 * o],     l0);
        l1 = fmaf(pv, w3[2 * o + 1], l1);
    }
    float m = fmaxf(l0, l1);
    float lse = m + logf(expf(l0 - m) + expf(l1 - m));
    out[2 * g]     = l0 - lse;
    out[2 * g + 1] = l1 - lse;
}

// ---------------------------------------------------------------------------
extern "C" void kernel_launch(void* const* d_in, const int* in_sizes, int n_in,
                              void* d_out, int out_size) {
    const float* x   = (const float*)d_in[0];
    const float* eps = (const float*)d_in[1];
    const float* w1  = (const float*)d_in[2];
    const float* b1  = (const float*)d_in[3];
    const float* g1  = (const float*)d_in[4];
    const float* be1 = (const float*)d_in[5];
    const float* m1  = (const float*)d_in[6];
    const float* v1  = (const float*)d_in[7];
    const float* w2  = (const float*)d_in[8];
    const float* b2  = (const float*)d_in[9];
    const float* g2  = (const float*)d_in[10];
    const float* be2 = (const float*)d_in[11];
    const float* m2  = (const float*)d_in[12];
    const float* v2  = (const float*)d_in[13];
    const float* w3  = (const float*)d_in[14];
    const float* b3  = (const float*)d_in[15];
    const int*   ei  = (const int*)d_in[16];
    const int*   batch = (const int*)d_in[17];

    int n = in_sizes[0] / 4;
    int E = in_sizes[16] / 2;
    int G = out_size / 2;

    static int smem_set = 0;
    if (!smem_set) {
        cudaFuncSetAttribute(mlp_kernel, cudaFuncAttributeMaxDynamicSharedMemorySize, MLP_SMEM);
        smem_set = 1;
    }

    int piCover = n;
    if (G * HID > piCover) piCover = G * HID;
    if (32 * 256 > piCover) piCover = 32 * 256;
    prep_init_kernel<<<(piCover + 255) / 256, 256>>>((const float4*)x, eps,
                                                w1, b1, g1, be1, m1, v1,
                                                w2, b2, g2, be2, m2, v2, n, G);
    int et = (E + 7) / 8;
    edge_kernel<<<(et + 255) / 256, 256>>>(ei, (const float4*)x, E);
    int numTiles = (n + 255) / 256;
    int mlpGrid = 296;                      // 2 CTAs x 148 SMs
    if (mlpGrid > numTiles) mlpGrid = numTiles;
    mlp_kernel<<<mlpGrid, 256, MLP_SMEM>>>(batch, n, numTiles);
    final_kernel<<<(G + 255) / 256, 256>>>(w3, b3, (float*)d_out, G);
}

// round 8
// speedup vs baseline: 1.3312x; 1.0465x over previous
#include <cuda_runtime.h>

#define NMAX 500000
#define GMAX 5000
#define HID 64
#define H1  128

// Scratch (static __device__ per allocation rules)
__device__ float4 d_agg[NMAX];           // (1+eps)*x + sum_{j->i} x_j
__device__ float  d_sums[GMAX * HID];    // per-graph h2 sums
__device__ float  d_cnt[GMAX];           // per-graph node counts (as float)
__device__ float  d_W1f[32 * 32];        // layer1 B-fragments (W1+bias row), per-lane order
__device__ float  d_Bfrag[32 * 256];     // W2 in per-lane mma fragment order (K-permuted)
__device__ float  d_C2[HID];             // folded bias2

__device__ __forceinline__ unsigned f2tf(float f) {
    unsigned r;
    asm("cvt.rna.tf32.f32 %0, %1;" : "=r"(r) : "f"(f));
    return r;
}

__device__ __forceinline__ void red4(float4* p, float4 v) {
    asm volatile("red.global.add.v4.f32 [%0], {%1, %2, %3, %4};"
                 :: "l"(p), "f"(v.x), "f"(v.y), "f"(v.z), "f"(v.w)
                 : "memory");
}

__device__ __forceinline__ void redf(float* p, float v) {
    asm volatile("red.global.add.f32 [%0], %1;" :: "l"(p), "f"(v) : "memory");
}

__device__ __forceinline__ void mma_tf32(float* c, unsigned a0, unsigned a1,
                                         unsigned a2, unsigned a3,
                                         unsigned b0, unsigned b1) {
    asm volatile(
        "mma.sync.aligned.m16n8k8.row.col.f32.tf32.tf32.f32 "
        "{%0,%1,%2,%3},{%4,%5,%6,%7},{%8,%9},{%0,%1,%2,%3};"
        : "+f"(c[0]), "+f"(c[1]), "+f"(c[2]), "+f"(c[3])
        : "r"(a0), "r"(a1), "r"(a2), "r"(a3), "r"(b0), "r"(b1));
}

// ---------------------------------------------------------------------------
// Merged prep + init: fold BN into weights (low blocks) AND initialize
// agg[i] = (1+eps)*x[i] (all blocks). Zero pooling accumulators + counts.
// ---------------------------------------------------------------------------
__global__ void prep_init_kernel(const float4* __restrict__ x, const float* __restrict__ epsp,
                            const float* __restrict__ w1, const float* __restrict__ b1,
                            const float* __restrict__ g1, const float* __restrict__ be1,
                            const float* __restrict__ m1, const float* __restrict__ v1,
                            const float* __restrict__ w2, const float* __restrict__ b2,
                            const float* __restrict__ g2, const float* __restrict__ be2,
                            const float* __restrict__ m2, const float* __restrict__ v2,
                            int n, int G) {
    int idx = blockIdx.x * blockDim.x + threadIdx.x;
    if (idx < n) {
        float c = 1.f + *epsp;
        float4 v = x[idx];
        v.x *= c; v.y *= c; v.z *= c; v.w *= c;
        d_agg[idx] = v;
    }
    if (idx < G * HID) d_sums[idx] = 0.f;
    if (idx < G) d_cnt[idx] = 0.f;
    if (idx < 32 * 256) {
        int l = idx >> 8, q = idx & 255;
        int kc = l & 3, grp = l >> 2;
        int s = q >> 4, r = q & 15, nt = r >> 1, j = r & 1;
        int k = 8 * s + 2 * kc + j;          // K-permuted
        int o = 8 * nt + grp;
        float s2 = g2[o] * rsqrtf(v2[o] + 1e-5f);
        d_Bfrag[idx] = __uint_as_float(f2tf(w2[k * HID + o] * s2));
    }
    if (idx < 32 * 32) {
        int l = idx >> 5, q = idx & 31;
        int kc = l & 3, grp = l >> 2;
        int nt = q >> 1, j = q & 1;
        int col = 8 * nt + grp;
        float s1 = g1[col] * rsqrtf(v1[col] + 1e-5f);
        float val;
        if (j == 0)       val = w1[kc * H1 + col] * s1;
        else if (kc == 0) val = (b1[col] - m1[col]) * s1 + be1[col];
        else              val = 0.f;
        d_W1f[idx] = __uint_as_float(f2tf(val));
    }
    if (idx < HID) {
        float s2 = g2[idx] * rsqrtf(v2[idx] + 1e-5f);
        d_C2[idx] = (b2[idx] - m2[idx]) * s2 + be2[idx];
    }
}

// ---------------------------------------------------------------------------
// Edge scatter: agg[dst] += x[src], one vectorized RED per edge, 8 edges/thread.
// ---------------------------------------------------------------------------
__global__ void edge_kernel(const int* __restrict__ ei, const float4* __restrict__ x, int E) {
    int t = blockIdx.x * blockDim.x + threadIdx.x;
    int e = t * 8;
    if (e + 7 < E) {
        int4 s0 = __ldcs((const int4*)(ei + e));
        int4 s1 = __ldcs((const int4*)(ei + e + 4));
        int4 d0 = __ldcs((const int4*)(ei + E + e));
        int4 d1 = __ldcs((const int4*)(ei + E + e + 4));
        float4 v0 = __ldg(x + s0.x);
        float4 v1 = __ldg(x + s0.y);
        float4 v2 = __ldg(x + s0.z);
        float4 v3 = __ldg(x + s0.w);
        float4 v4 = __ldg(x + s1.x);
        float4 v5 = __ldg(x + s1.y);
        float4 v6 = __ldg(x + s1.z);
        float4 v7 = __ldg(x + s1.w);
        red4(&d_agg[d0.x], v0);
        red4(&d_agg[d0.y], v1);
        red4(&d_agg[d0.z], v2);
        red4(&d_agg[d0.w], v3);
        red4(&d_agg[d1.x], v4);
        red4(&d_agg[d1.y], v5);
        red4(&d_agg[d1.z], v6);
        red4(&d_agg[d1.w], v7);
    } else if (e < E) {
        for (int q = e; q < E; q++) {
            int s = ei[q], d = ei[E + q];
            red4(&d_agg[d], __ldg(x + s));
        }
    }
}

// ---------------------------------------------------------------------------
// Persistent fused MLP + pool, all-tensor path, software-pipelined across
// tiles. Pooling scan also accumulates per-graph node counts.
// ---------------------------------------------------------------------------
#define SM_BF   (32 * 260)          // layer2 B fragments
#define SM_W1   (32 * 34)           // layer1 B fragments
#define SM_H2   (256 * 68)          // h2 staging, stride 68 (16B-aligned rows)
#define MLP_SMEM_F (SM_BF + SM_W1 + SM_H2 + 64 + 256)
#define MLP_SMEM (MLP_SMEM_F * 4)

__global__ void __launch_bounds__(256, 2)
mlp_kernel(const int* __restrict__ batch, int n, int numTiles) {
    extern __shared__ float sm[];
    float*  Bf   = sm;                       // [32][260]
    float*  W1s  = sm + SM_BF;               // [32][34]
    float*  h2s  = sm + SM_BF + SM_W1;       // [256][68]
    float*  C2s  = sm + SM_BF + SM_W1 + SM_H2;
    int*    batchs = (int*)(C2s + 64);

    int tid = threadIdx.x;
    int lane = tid & 31, warp = tid >> 5;
    int grp = lane >> 2;      // lane / 4
    int kc  = lane & 3;       // lane % 4

    for (int i = tid; i < 32 * 256; i += 256) {
        int l = i >> 8, q = i & 255;
        Bf[l * 260 + q] = d_Bfrag[i];
    }
    for (int i = tid; i < 32 * 32; i += 256) {
        int l = i >> 5, q = i & 31;
        W1s[l * 34 + q] = d_W1f[i];
    }
    if (tid < HID) C2s[tid] = d_C2[tid];

    const float4* bptr  = (const float4*)(Bf + lane * 260);
    const float2* w1ptr = (const float2*)(W1s + lane * 34);
    const float*  xs    = (const float*)d_agg;
    unsigned A2 = (kc == 0) ? 0x3F800000u : 0u;   // bias-row A value (tf32 1.0)

    // prologue prefetch for first tile
    float pv[4];
    int   pb;
    {
        int tile0 = blockIdx.x;
        int rb = tile0 * 256 + warp * 32 + grp;
        #pragma unroll
        for (int t = 0; t < 4; t++) pv[t] = xs[min(rb + 8 * t, n - 1) * 4 + kc];
        int nd = tile0 * 256 + tid;
        pb = (nd < n) ? batch[nd] : -1;
    }

    for (int tile = blockIdx.x; tile < numTiles; tile += gridDim.x) {
        __syncthreads();   // weights ready (first iter) / prior scan done

        batchs[tid] = pb;

        unsigned a0[2], a1[2];
        a0[0] = f2tf(pv[0]); a1[0] = f2tf(pv[1]);
        a0[1] = f2tf(pv[2]); a1[1] = f2tf(pv[3]);

        // issue prefetch for the NEXT tile now; consumed after this tile's work
        {
            int tile2 = tile + gridDim.x;
            int tc = min(tile2, numTiles - 1);
            int rb = tc * 256 + warp * 32 + grp;
            #pragma unroll
            for (int t = 0; t < 4; t++) pv[t] = xs[min(rb + 8 * t, n - 1) * 4 + kc];
            int nd = tile2 * 256 + tid;
            pb = (tile2 < numTiles && nd < n) ? batch[min(nd, n - 1)] : -1;
        }

        float acc[2][8][4];
        #pragma unroll
        for (int t = 0; t < 2; t++)
            #pragma unroll
            for (int nt = 0; nt < 8; nt++)
                #pragma unroll
                for (int i = 0; i < 4; i++) acc[t][nt][i] = 0.f;

        #pragma unroll
        for (int s = 0; s < 16; s++) {
            // layer1 mma for h1 col-group s (8 cols)
            float2 bw = w1ptr[s];
            unsigned bb0 = __float_as_uint(bw.x), bb1 = __float_as_uint(bw.y);
            float d1[2][4] = {{0.f,0.f,0.f,0.f},{0.f,0.f,0.f,0.f}};
            mma_tf32(d1[0], a0[0], a1[0], A2, A2, bb0, bb1);
            mma_tf32(d1[1], a0[1], a1[1], A2, A2, bb0, bb1);
            // relu -> layer2 A-frags; raw f32 bits act as truncated tf32
            unsigned f0[2], f1[2], f2v[2], f3[2];
            #pragma unroll
            for (int t = 0; t < 2; t++) {
                f0[t]  = __float_as_uint(fmaxf(d1[t][0], 0.f));
                f2v[t] = __float_as_uint(fmaxf(d1[t][1], 0.f));
                f1[t]  = __float_as_uint(fmaxf(d1[t][2], 0.f));
                f3[t]  = __float_as_uint(fmaxf(d1[t][3], 0.f));
            }
            // layer2: 8 n-tiles
            #pragma unroll
            for (int np = 0; np < 4; np++) {
                float4 bv = bptr[s * 4 + np];
                unsigned bx = __float_as_uint(bv.x), by = __float_as_uint(bv.y);
                unsigned bz = __float_as_uint(bv.z), bwv = __float_as_uint(bv.w);
                #pragma unroll
                for (int t = 0; t < 2; t++) {
                    mma_tf32(acc[t][2 * np],     f0[t], f1[t], f2v[t], f3[t], bx, by);
                    mma_tf32(acc[t][2 * np + 1], f0[t], f1[t], f2v[t], f3[t], bz, bwv);
                }
            }
        }

        // epilogue: bias + relu, float2 stores into h2 staging
        int r0l = warp * 32 + grp;
        #pragma unroll
        for (int t = 0; t < 2; t++) {
            int rl = r0l + 16 * t;
            #pragma unroll
            for (int nt = 0; nt < 8; nt++) {
                int c = nt * 8 + 2 * kc;
                float2 lo = make_float2(fmaxf(acc[t][nt][0] + C2s[c], 0.f),
                                        fmaxf(acc[t][nt][1] + C2s[c + 1], 0.f));
                float2 hi = make_float2(fmaxf(acc[t][nt][2] + C2s[c], 0.f),
                                        fmaxf(acc[t][nt][3] + C2s[c + 1], 0.f));
                *(float2*)&h2s[rl * 68 + c]       = lo;
                *(float2*)&h2s[(rl + 8) * 68 + c] = hi;
            }
        }
        __syncthreads();

        // segmented pooling scan: thread = (4-col group, 16-row part).
        // Col-leader threads also accumulate per-graph node counts.
        int col4 = (tid & 15) * 4;
        int part = tid >> 4;            // 0..15
        bool leader = (tid & 15) == 0;
        float4 run = make_float4(0.f, 0.f, 0.f, 0.f);
        float cnt = 0.f;
        int curg = -1;
        #pragma unroll
        for (int i = 0; i < 16; i++) {
            int ln = part * 16 + i;
            int g = batchs[ln];
            if (g != curg) {
                if (curg >= 0) {
                    red4((float4*)&d_sums[curg * HID + col4], run);
                    if (leader) redf(&d_cnt[curg], cnt);
                }
                if (g < 0) { curg = -1; break; }
                run = make_float4(0.f, 0.f, 0.f, 0.f);
                cnt = 0.f;
                curg = g;
            }
            float4 v = *(const float4*)&h2s[ln * 68 + col4];
            run.x += v.x; run.y += v.y; run.z += v.z; run.w += v.w;
            cnt += 1.f;
        }
        if (curg >= 0) {
            red4((float4*)&d_sums[curg * HID + col4], run);
            if (leader) redf(&d_cnt[curg], cnt);
        }
    }
}

// ---------------------------------------------------------------------------
// Final: warp-per-graph. Each lane handles 2 of the 64 hidden channels
// (coalesced), butterfly-reduces the two logits, lane 0 writes log_softmax.
// ---------------------------------------------------------------------------
__global__ void final_kernel(const float* __restrict__ w3, const float* __restrict__ b3,
                             float* __restrict__ out, int G) {
    int gw = (blockIdx.x * blockDim.x + threadIdx.x) >> 5;
    int lane = threadIdx.x & 31;
    if (gw >= G) return;

    float inv = 1.f / fmaxf(d_cnt[gw], 1.f);
    const float* sp = &d_sums[gw * HID];
    float a = sp[lane]      * inv;
    float b = sp[lane + 32] * inv;
    float w0a = __ldg(&w3[2 * lane]);
    float w1a = __ldg(&w3[2 * lane + 1]);
    float w0b = __ldg(&w3[2 * (lane + 32)]);
    float w1b = __ldg(&w3[2 * (lane + 32) + 1]);
    float l0 = fmaf(a, w0a, b * w0b);
    float l1 = fmaf(a, w1a, b * w1b);
    #pragma unroll
    for (int off = 16; off; off >>= 1) {
        l0 += __shfl_xor_sync(0xFFFFFFFFu, l0, off);
        l1 += __shfl_xor_sync(0xFFFFFFFFu, l1, off);
    }
    if (lane == 0) {
        l0 += __ldg(&b3[0]);
        l1 += __ldg(&b3[1]);
        float m = fmaxf(l0, l1);
        float lse = m + logf(expf(l0 - m) + expf(l1 - m));
        *(float2*)&out[2 * gw] = make_float2(l0 - lse, l1 - lse);
    }
}

// ---------------------------------------------------------------------------
extern "C" void kernel_launch(void* const* d_in, const int* in_sizes, int n_in,
                              void* d_out, int out_size) {
    const float* x   = (const float*)d_in[0];
    const float* eps = (const float*)d_in[1];
    const float* w1  = (const float*)d_in[2];
    const float* b1  = (const float*)d_in[3];
    const float* g1  = (const float*)d_in[4];
    const float* be1 = (const float*)d_in[5];
    const float* m1  = (const float*)d_in[6];
    const float* v1  = (const float*)d_in[7];
    const float* w2  = (const float*)d_in[8];
    const float* b2  = (const float*)d_in[9];
    const float* g2  = (const float*)d_in[10];
    const float* be2 = (const float*)d_in[11];
    const float* m2  = (const float*)d_in[12];
    const float* v2  = (const float*)d_in[13];
    const float* w3  = (const float*)d_in[14];
    const float* b3  = (const float*)d_in[15];
    const int*   ei  = (const int*)d_in[16];
    const int*   batch = (const int*)d_in[17];

    int n = in_sizes[0] / 4;
    int E = in_sizes[16] / 2;
    int G = out_size / 2;

    static int smem_set = 0;
    if (!smem_set) {
        cudaFuncSetAttribute(mlp_kernel, cudaFuncAttributeMaxDynamicSharedMemorySize, MLP_SMEM);
        smem_set = 1;
    }

    int piCover = n;
    if (G * HID > piCover) piCover = G * HID;
    if (32 * 256 > piCover) piCover = 32 * 256;
    prep_init_kernel<<<(piCover + 255) / 256, 256>>>((const float4*)x, eps,
                                                w1, b1, g1, be1, m1, v1,
                                                w2, b2, g2, be2, m2, v2, n, G);
    int et = (E + 7) / 8;
    edge_kernel<<<(et + 255) / 256, 256>>>(ei, (const float4*)x, E);
    int numTiles = (n + 255) / 256;
    int mlpGrid = 296;                      // 2 CTAs x 148 SMs
    if (mlpGrid > numTiles) mlpGrid = numTiles;
    mlp_kernel<<<mlpGrid, 256, MLP_SMEM>>>(batch, n, numTiles);
    final_kernel<<<(G * 32 + 255) / 256, 256>>>(w3, b3, (float*)d_out, G);
}

// round 9
// speedup vs baseline: 1.4721x; 1.1059x over previous
#include <cuda_runtime.h>
#include <cuda_fp16.h>

#define NMAX 500000
#define GMAX 5000
#define HID 64
#define H1  128

// Scratch (static __device__ per allocation rules)
__device__ float4   d_agg[NMAX];         // (1+eps)*x + sum_{j->i} x_j
__device__ float    d_sums[GMAX * HID];  // per-graph h2 sums
__device__ float    d_cnt[GMAX];         // per-graph node counts (as float)
__device__ float    d_W1f[32 * 32];      // layer1 B-fragments (W1+bias row), per-lane order
__device__ unsigned d_Bfrag[32 * 128];   // W2 as f16x2 m16n8k16 B-fragments, per-lane order
__device__ float    d_C2[HID];           // folded bias2

__device__ __forceinline__ unsigned f2tf(float f) {
    unsigned r;
    asm("cvt.rna.tf32.f32 %0, %1;" : "=r"(r) : "f"(f));
    return r;
}

__device__ __forceinline__ void red4(float4* p, float4 v) {
    asm volatile("red.global.add.v4.f32 [%0], {%1, %2, %3, %4};"
                 :: "l"(p), "f"(v.x), "f"(v.y), "f"(v.z), "f"(v.w)
                 : "memory");
}

__device__ __forceinline__ void redf(float* p, float v) {
    asm volatile("red.global.add.f32 [%0], %1;" :: "l"(p), "f"(v) : "memory");
}

__device__ __forceinline__ void mma_tf32(float* c, unsigned a0, unsigned a1,
                                         unsigned a2, unsigned a3,
                                         unsigned b0, unsigned b1) {
    asm volatile(
        "mma.sync.aligned.m16n8k8.row.col.f32.tf32.tf32.f32 "
        "{%0,%1,%2,%3},{%4,%5,%6,%7},{%8,%9},{%0,%1,%2,%3};"
        : "+f"(c[0]), "+f"(c[1]), "+f"(c[2]), "+f"(c[3])
        : "r"(a0), "r"(a1), "r"(a2), "r"(a3), "r"(b0), "r"(b1));
}

__device__ __forceinline__ void mma_f16(float* c, unsigned a0, unsigned a1,
                                        unsigned a2, unsigned a3,
                                        unsigned b0, unsigned b1) {
    asm volatile(
        "mma.sync.aligned.m16n8k16.row.col.f32.f16.f16.f32 "
        "{%0,%1,%2,%3},{%4,%5,%6,%7},{%8,%9},{%0,%1,%2,%3};"
        : "+f"(c[0]), "+f"(c[1]), "+f"(c[2]), "+f"(c[3])
        : "r"(a0), "r"(a1), "r"(a2), "r"(a3), "r"(b0), "r"(b1));
}

// pack two f32 into half2 (lo, hi) with relu applied in half2
__device__ __forceinline__ unsigned pack_relu_h2(float lo, float hi) {
    __half2 v = __floats2half2_rn(lo, hi);
    __half2 z = __half2half2(__ushort_as_half((unsigned short)0));
    v = __hmax2(v, z);
    return *reinterpret_cast<unsigned*>(&v);
}

// ---------------------------------------------------------------------------
// Merged prep + init: fold BN into weights (low blocks) AND initialize
// agg[i] = (1+eps)*x[i] (all blocks). Zero pooling accumulators + counts.
// Layer1 B-frags (tf32 m16n8k8): lane l (kc=l&3, grp=l>>2), q = 2*nt + j:
//   j=0 -> W1fold[k=kc][col=8nt+grp]      j=1 -> kc==0 ? C1fold[col] : 0
// Layer2 B-frags (f16 m16n8k16), identity K-map: q = u*16 + nt*2 + j:
//   value = half2( W2f[16u+8j+2kc][o], W2f[16u+8j+2kc+1][o] ), o = 8nt+grp
// ---------------------------------------------------------------------------
__global__ void prep_init_kernel(const float4* __restrict__ x, const float* __restrict__ epsp,
                            const float* __restrict__ w1, const float* __restrict__ b1,
                            const float* __restrict__ g1, const float* __restrict__ be1,
                            const float* __restrict__ m1, const float* __restrict__ v1,
                            const float* __restrict__ w2, const float* __restrict__ b2,
                            const float* __restrict__ g2, const float* __restrict__ be2,
                            const float* __restrict__ m2, const float* __restrict__ v2,
                            int n, int G) {
    int idx = blockIdx.x * blockDim.x + threadIdx.x;
    if (idx < n) {
        float c = 1.f + *epsp;
        float4 v = x[idx];
        v.x *= c; v.y *= c; v.z *= c; v.w *= c;
        d_agg[idx] = v;
    }
    if (idx < G * HID) d_sums[idx] = 0.f;
    if (idx < G) d_cnt[idx] = 0.f;
    if (idx < 32 * 128) {
        int l = idx >> 7, q = idx & 127;
        int kc = l & 3, grp = l >> 2;
        int u = q >> 4, r = q & 15, nt = r >> 1, j = r & 1;
        int k0 = 16 * u + 8 * j + 2 * kc;
        int o = 8 * nt + grp;
        float s2 = g2[o] * rsqrtf(v2[o] + 1e-5f);
        __half2 h = __floats2half2_rn(w2[k0 * HID + o] * s2, w2[(k0 + 1) * HID + o] * s2);
        d_Bfrag[idx] = *reinterpret_cast<unsigned*>(&h);
    }
    if (idx < 32 * 32) {
        int l = idx >> 5, q = idx & 31;
        int kc = l & 3, grp = l >> 2;
        int nt = q >> 1, j = q & 1;
        int col = 8 * nt + grp;
        float s1 = g1[col] * rsqrtf(v1[col] + 1e-5f);
        float val;
        if (j == 0)       val = w1[kc * H1 + col] * s1;
        else if (kc == 0) val = (b1[col] - m1[col]) * s1 + be1[col];
        else              val = 0.f;
        d_W1f[idx] = __uint_as_float(f2tf(val));
    }
    if (idx < HID) {
        float s2 = g2[idx] * rsqrtf(v2[idx] + 1e-5f);
        d_C2[idx] = (b2[idx] - m2[idx]) * s2 + be2[idx];
    }
}

// ---------------------------------------------------------------------------
// Edge scatter: agg[dst] += x[src], one vectorized RED per edge, 8 edges/thread.
// ---------------------------------------------------------------------------
__global__ void edge_kernel(const int* __restrict__ ei, const float4* __restrict__ x, int E) {
    int t = blockIdx.x * blockDim.x + threadIdx.x;
    int e = t * 8;
    if (e + 7 < E) {
        int4 s0 = __ldcs((const int4*)(ei + e));
        int4 s1 = __ldcs((const int4*)(ei + e + 4));
        int4 d0 = __ldcs((const int4*)(ei + E + e));
        int4 d1 = __ldcs((const int4*)(ei + E + e + 4));
        float4 v0 = __ldg(x + s0.x);
        float4 v1 = __ldg(x + s0.y);
        float4 v2 = __ldg(x + s0.z);
        float4 v3 = __ldg(x + s0.w);
        float4 v4 = __ldg(x + s1.x);
        float4 v5 = __ldg(x + s1.y);
        float4 v6 = __ldg(x + s1.z);
        float4 v7 = __ldg(x + s1.w);
        red4(&d_agg[d0.x], v0);
        red4(&d_agg[d0.y], v1);
        red4(&d_agg[d0.z], v2);
        red4(&d_agg[d0.w], v3);
        red4(&d_agg[d1.x], v4);
        red4(&d_agg[d1.y], v5);
        red4(&d_agg[d1.z], v6);
        red4(&d_agg[d1.w], v7);
    } else if (e < E) {
        for (int q = e; q < E; q++) {
            int s = ei[q], d = ei[E + q];
            red4(&d_agg[d], __ldg(x + s));
        }
    }
}

// ---------------------------------------------------------------------------
// Persistent fused MLP + pool. Layer1: tf32 m16n8k8 (A=[x,1,0,0,0], bias via
// K row). Layer1 acc pairs (cols 2kc,2kc+1) pack DIRECTLY into f16 m16n8k16
// A-fragments (identity K-map). Layer2: f16 m16n8k16, half the mma count of
// the tf32 path. Pool: float4 segmented scan + red.v4 + counts.
// ---------------------------------------------------------------------------
#define SM_BF   (32 * 132)          // layer2 B fragments (uint32 half2), padded
#define SM_W1   (32 * 34)           // layer1 B fragments
#define SM_H2   (256 * 68)          // h2 staging, stride 68 (16B-aligned rows)
#define MLP_SMEM_F (SM_BF + SM_W1 + SM_H2 + 64 + 256)
#define MLP_SMEM (MLP_SMEM_F * 4)

__global__ void __launch_bounds__(256, 2)
mlp_kernel(const int* __restrict__ batch, int n, int numTiles) {
    extern __shared__ float sm[];
    unsigned* Bf  = (unsigned*)sm;           // [32][132]
    float*  W1s  = sm + SM_BF;               // [32][34]
    float*  h2s  = sm + SM_BF + SM_W1;       // [256][68]
    float*  C2s  = sm + SM_BF + SM_W1 + SM_H2;
    int*    batchs = (int*)(C2s + 64);

    int tid = threadIdx.x;
    int lane = tid & 31, warp = tid >> 5;
    int grp = lane >> 2;      // lane / 4
    int kc  = lane & 3;       // lane % 4

    for (int i = tid; i < 32 * 128; i += 256) {
        int l = i >> 7, q = i & 127;
        Bf[l * 132 + q] = d_Bfrag[i];
    }
    for (int i = tid; i < 32 * 32; i += 256) {
        int l = i >> 5, q = i & 31;
        W1s[l * 34 + q] = d_W1f[i];
    }
    if (tid < HID) C2s[tid] = d_C2[tid];

    const uint4*  bptr  = (const uint4*)(Bf + lane * 132);
    const float2* w1ptr = (const float2*)(W1s + lane * 34);
    const float*  xs    = (const float*)d_agg;
    unsigned A2 = (kc == 0) ? 0x3F800000u : 0u;   // bias-row A value (tf32 1.0)

    // prologue prefetch for first tile
    float pv[4];
    int   pb;
    {
        int tile0 = blockIdx.x;
        int rb = tile0 * 256 + warp * 32 + grp;
        #pragma unroll
        for (int t = 0; t < 4; t++) pv[t] = xs[min(rb + 8 * t, n - 1) * 4 + kc];
        int nd = tile0 * 256 + tid;
        pb = (nd < n) ? batch[nd] : -1;
    }

    for (int tile = blockIdx.x; tile < numTiles; tile += gridDim.x) {
        __syncthreads();   // weights ready (first iter) / prior scan done

        batchs[tid] = pb;

        unsigned a0[2], a1[2];
        a0[0] = f2tf(pv[0]); a1[0] = f2tf(pv[1]);
        a0[1] = f2tf(pv[2]); a1[1] = f2tf(pv[3]);

        // issue prefetch for the NEXT tile now; consumed after this tile's work
        {
            int tile2 = tile + gridDim.x;
            int tc = min(tile2, numTiles - 1);
            int rb = tc * 256 + warp * 32 + grp;
            #pragma unroll
            for (int t = 0; t < 4; t++) pv[t] = xs[min(rb + 8 * t, n - 1) * 4 + kc];
            int nd = tile2 * 256 + tid;
            pb = (tile2 < numTiles && nd < n) ? batch[min(nd, n - 1)] : -1;
        }

        float acc[2][8][4];
        #pragma unroll
        for (int t = 0; t < 2; t++)
            #pragma unroll
            for (int nt = 0; nt < 8; nt++)
                #pragma unroll
                for (int i = 0; i < 4; i++) acc[t][nt][i] = 0.f;

        #pragma unroll
        for (int u = 0; u < 8; u++) {
            // A fragments for K-window [16u, 16u+16): Af[slot][Mtile]
            unsigned Af[4][2];
            #pragma unroll
            for (int h = 0; h < 2; h++) {       // s = 2u + h (8 h1 cols each)
                float2 bw = w1ptr[2 * u + h];
                unsigned bb0 = __float_as_uint(bw.x), bb1 = __float_as_uint(bw.y);
                #pragma unroll
                for (int t = 0; t < 2; t++) {
                    float d1[4] = {0.f, 0.f, 0.f, 0.f};
                    mma_tf32(d1, a0[t], a1[t], A2, A2, bb0, bb1);
                    // c0,c1 = (row grp, cols 2kc,2kc+1); c2,c3 = (row grp+8)
                    Af[2 * h][t]     = pack_relu_h2(d1[0], d1[1]);  // a0 / a2
                    Af[2 * h + 1][t] = pack_relu_h2(d1[2], d1[3]);  // a1 / a3
                }
            }
            // layer2: f16 k16 mma, 8 n-tiles
            #pragma unroll
            for (int np = 0; np < 4; np++) {
                uint4 bv = bptr[u * 4 + np];
                #pragma unroll
                for (int t = 0; t < 2; t++) {
                    mma_f16(acc[t][2 * np],     Af[0][t], Af[1][t], Af[2][t], Af[3][t], bv.x, bv.y);
                    mma_f16(acc[t][2 * np + 1], Af[0][t], Af[1][t], Af[2][t], Af[3][t], bv.z, bv.w);
                }
            }
        }

        // epilogue: bias + relu, float2 stores into h2 staging
        int r0l = warp * 32 + grp;
        #pragma unroll
        for (int t = 0; t < 2; t++) {
            int rl = r0l + 16 * t;
            #pragma unroll
            for (int nt = 0; nt < 8; nt++) {
                int c = nt * 8 + 2 * kc;
                float2 lo = make_float2(fmaxf(acc[t][nt][0] + C2s[c], 0.f),
                                        fmaxf(acc[t][nt][1] + C2s[c + 1], 0.f));
                float2 hi = make_float2(fmaxf(acc[t][nt][2] + C2s[c], 0.f),
                                        fmaxf(acc[t][nt][3] + C2s[c + 1], 0.f));
                *(float2*)&h2s[rl * 68 + c]       = lo;
                *(float2*)&h2s[(rl + 8) * 68 + c] = hi;
            }
        }
        __syncthreads();

        // segmented pooling scan: thread = (4-col group, 16-row part).
        // Col-leader threads also accumulate per-graph node counts.
        int col4 = (tid & 15) * 4;
        int part = tid >> 4;            // 0..15
        bool leader = (tid & 15) == 0;
        float4 run = make_float4(0.f, 0.f, 0.f, 0.f);
        float cnt = 0.f;
        int curg = -1;
        #pragma unroll
        for (int i = 0; i < 16; i++) {
            int ln = part * 16 + i;
            int g = batchs[ln];
            if (g != curg) {
                if (curg >= 0) {
                    red4((float4*)&d_sums[curg * HID + col4], run);
                    if (leader) redf(&d_cnt[curg], cnt);
                }
                if (g < 0) { curg = -1; break; }
                run = make_float4(0.f, 0.f, 0.f, 0.f);
                cnt = 0.f;
                curg = g;
            }
            float4 v = *(const float4*)&h2s[ln * 68 + col4];
            run.x += v.x; run.y += v.y; run.z += v.z; run.w += v.w;
            cnt += 1.f;
        }
        if (curg >= 0) {
            red4((float4*)&d_sums[curg * HID + col4], run);
            if (leader) redf(&d_cnt[curg], cnt);
        }
    }
}

// ---------------------------------------------------------------------------
// Final: warp-per-graph. Each lane handles 2 of the 64 hidden channels
// (coalesced), butterfly-reduces the two logits, lane 0 writes log_softmax.
// ---------------------------------------------------------------------------
__global__ void final_kernel(const float* __restrict__ w3, const float* __restrict__ b3,
                             float* __restrict__ out, int G) {
    int gw = (blockIdx.x * blockDim.x + threadIdx.x) >> 5;
    int lane = threadIdx.x & 31;
    if (gw >= G) return;

    float inv = 1.f / fmaxf(d_cnt[gw], 1.f);
    const float* sp = &d_sums[gw * HID];
    float a = sp[lane]      * inv;
    float b = sp[lane + 32] * inv;
    float w0a = __ldg(&w3[2 * lane]);
    float w1a = __ldg(&w3[2 * lane + 1]);
    float w0b = __ldg(&w3[2 * (lane + 32)]);
    float w1b = __ldg(&w3[2 * (lane + 32) + 1]);
    float l0 = fmaf(a, w0a, b * w0b);
    float l1 = fmaf(a, w1a, b * w1b);
    #pragma unroll
    for (int off = 16; off; off >>= 1) {
        l0 += __shfl_xor_sync(0xFFFFFFFFu, l0, off);
        l1 += __shfl_xor_sync(0xFFFFFFFFu, l1, off);
    }
    if (lane == 0) {
        l0 += __ldg(&b3[0]);
        l1 += __ldg(&b3[1]);
        float m = fmaxf(l0, l1);
        float lse = m + logf(expf(l0 - m) + expf(l1 - m));
        *(float2*)&out[2 * gw] = make_float2(l0 - lse, l1 - lse);
    }
}

// ---------------------------------------------------------------------------
extern "C" void kernel_launch(void* const* d_in, const int* in_sizes, int n_in,
                              void* d_out, int out_size) {
    const float* x   = (const float*)d_in[0];
    const float* eps = (const float*)d_in[1];
    const float* w1  = (const float*)d_in[2];
    const float* b1  = (const float*)d_in[3];
    const float* g1  = (const float*)d_in[4];
    const float* be1 = (const float*)d_in[5];
    const float* m1  = (const float*)d_in[6];
    const float* v1  = (const float*)d_in[7];
    const float* w2  = (const float*)d_in[8];
    const float* b2  = (const float*)d_in[9];
    const float* g2  = (const float*)d_in[10];
    const float* be2 = (const float*)d_in[11];
    const float* m2  = (const float*)d_in[12];
    const float* v2  = (const float*)d_in[13];
    const float* w3  = (const float*)d_in[14];
    const float* b3  = (const float*)d_in[15];
    const int*   ei  = (const int*)d_in[16];
    const int*   batch = (const int*)d_in[17];

    int n = in_sizes[0] / 4;
    int E = in_sizes[16] / 2;
    int G = out_size / 2;

    static int smem_set = 0;
    if (!smem_set) {
        cudaFuncSetAttribute(mlp_kernel, cudaFuncAttributeMaxDynamicSharedMemorySize, MLP_SMEM);
        smem_set = 1;
    }

    int piCover = n;
    if (G * HID > piCover) piCover = G * HID;
    if (32 * 256 > piCover) piCover = 32 * 256;
    prep_init_kernel<<<(piCover + 255) / 256, 256>>>((const float4*)x, eps,
                                                w1, b1, g1, be1, m1, v1,
                                                w2, b2, g2, be2, m2, v2, n, G);
    int et = (E + 7) / 8;
    edge_kernel<<<(et + 255) / 256, 256>>>(ei, (const float4*)x, E);
    int numTiles = (n + 255) / 256;
    int mlpGrid = 296;                      // 2 CTAs x 148 SMs
    if (mlpGrid > numTiles) mlpGrid = numTiles;
    mlp_kernel<<<mlpGrid, 256, MLP_SMEM>>>(batch, n, numTiles);
    final_kernel<<<(G * 32 + 255) / 256, 256>>>(w3, b3, (float*)d_out, G);
}